// round 10
// baseline (speedup 1.0000x reference)
#include <cuda_runtime.h>
#include <cstdint>

// ---------------------------------------------------------------------------
// Playlist model:
//   12 embedding towers (3 single-lookup, 9 mean-pooled over L=100)
//   -> concat [B, 12*512] -> Dense(512) relu -> Dense(256) relu -> Dense(128)
//
// Structure:
//   * Small tables folded through W1 by linearity (P = T_small @ W1_slice,
//     88x512), bucket features via 21-bin histogram -> Y0 [B,512].
//   * Big GEMM1 runs K=3584 (7 big features) with an in-kernel K->W1 row map,
//     split-K=4, and a PACKED f32x2 inner loop (fma.rn.f32x2): the Blackwell
//     fma pipe retires 2 fp32 FMAs per instruction slot; ptxas never emits
//     FFMA2 from C++, so we do it via PTX. A-tile is stored duplicated in
//     smem so both MMA operands load as ready 64-bit lane pairs (no pack MOVs).
//   * Split-K partials + combine kernel (fixed-order sum => deterministic).
// ---------------------------------------------------------------------------

#define NB   1024
#define NL   100
#define KBIG 3584          // 7 * 512

__device__ float g_X   [NB * KBIG];
__device__ float g_Y0  [NB * 512];
__device__ float g_P   [88 * 512];
__device__ float g_H1  [NB * 512];
__device__ float g_H2  [NB * 256];
__device__ float g_part[4 * NB * 512];     // split-K partials (max 4 x 1024 x 512)

// W1 row offsets for the 7 big features in X-column order:
// name, track_can, artist_name, track_uri, track_name, album, genres
__constant__ int c_WOFF[7] = {0, 1024, 1536, 2048, 2560, 3584, 5632};

// packed dual-fp32 FMA: d.lo += a.lo*b.lo ; d.hi += a.hi*b.hi  (exact fp32)
__device__ __forceinline__ void ffma2(unsigned long long& d,
                                      unsigned long long a,
                                      unsigned long long b) {
    asm("fma.rn.f32x2 %0, %1, %2, %0;" : "+l"(d) : "l"(a), "l"(b));
}

// ---------------------------------------------------------------------------
__global__ void precompute_P(const float* __restrict__ T_collab,
                             const float* __restrict__ T_dur,
                             const float* __restrict__ T_apop,
                             const float* __restrict__ T_afol,
                             const float* __restrict__ T_tpop,
                             const float* __restrict__ W1) {
    __shared__ float s_t[512];
    int r = blockIdx.x;
    const float* T; int row; int off;
    if (r < 4)       { T = T_collab; row = r;      off = 512;  }
    else if (r < 25) { T = T_dur;    row = r - 4;  off = 3072; }
    else if (r < 46) { T = T_apop;   row = r - 25; off = 4096; }
    else if (r < 67) { T = T_afol;   row = r - 46; off = 4608; }
    else             { T = T_tpop;   row = r - 67; off = 5120; }
    int n = threadIdx.x;                       // 512 threads
    s_t[n] = T[row * 512 + n];
    __syncthreads();
    float acc = 0.0f;
    const float* w = W1 + (size_t)off * 512 + n;
    #pragma unroll 8
    for (int k = 0; k < 512; ++k)
        acc = fmaf(s_t[k], w[(size_t)k * 512], acc);
    g_P[r * 512 + n] = acc;
}

// ---------------------------------------------------------------------------
__global__ void small_pool(const int* __restrict__ id_collab,
                           const int* __restrict__ seq_dur,
                           const int* __restrict__ seq_apop,
                           const int* __restrict__ seq_afol,
                           const int* __restrict__ seq_tpop) {
    __shared__ int cnt[21];
    const int b = blockIdx.x, t = threadIdx.x;     // 128 threads, float4 lanes
    const float4* P4 = (const float4*)g_P;

    const int idc = id_collab[b];
    float4 acc = __ldg(&P4[(size_t)idc * 128 + t]);
    float4 ab  = make_float4(0.f, 0.f, 0.f, 0.f);

    const int* seqs[4]  = {seq_dur, seq_apop, seq_afol, seq_tpop};
    const int  pbase[4] = {4, 25, 46, 67};

    for (int j = 0; j < 4; ++j) {
        if (t < 21) cnt[t] = 0;
        __syncthreads();
        if (t < NL) atomicAdd(&cnt[seqs[j][b * NL + t]], 1);
        __syncthreads();
        #pragma unroll
        for (int v = 0; v < 21; ++v) {
            int c = cnt[v];
            if (c) {
                float fc = (float)c;
                float4 p = __ldg(&P4[(size_t)(pbase[j] + v) * 128 + t]);
                ab.x = fmaf(fc, p.x, ab.x);
                ab.y = fmaf(fc, p.y, ab.y);
                ab.z = fmaf(fc, p.z, ab.z);
                ab.w = fmaf(fc, p.w, ab.w);
            }
        }
        __syncthreads();
    }
    float4 o;
    o.x = acc.x + 0.01f * ab.x;
    o.y = acc.y + 0.01f * ab.y;
    o.z = acc.z + 0.01f * ab.z;
    o.w = acc.w + 0.01f * ab.w;
    ((float4*)g_Y0)[(size_t)b * 128 + t] = o;
}

// ---------------------------------------------------------------------------
struct BigArgs {
    const float* tbl[7];
    const int*   idx[7];
};

__global__ void __launch_bounds__(128) big_pool(BigArgs a) {
    const int b = blockIdx.x, f = blockIdx.y, t = threadIdx.x;   // 128 threads
    const float4* T = (const float4*)a.tbl[f];
    float4* dst = ((float4*)g_X) + (size_t)b * (KBIG / 4) + f * 128 + t;

    if (f < 2) {
        int id = a.idx[f][b];
        *dst = __ldg(&T[(size_t)id * 128 + t]);
        return;
    }
    __shared__ int s_idx[NL];
    if (t < NL) s_idx[t] = a.idx[f][b * NL + t];
    __syncthreads();

    float4 acc = make_float4(0.f, 0.f, 0.f, 0.f);
    #pragma unroll 10
    for (int l = 0; l < NL; ++l) {
        float4 v = __ldg(&T[(size_t)s_idx[l] * 128 + t]);
        acc.x += v.x; acc.y += v.y; acc.z += v.z; acc.w += v.w;
    }
    acc.x *= 0.01f; acc.y *= 0.01f; acc.z *= 0.01f; acc.w *= 0.01f;
    *dst = acc;
}

// ---------------------------------------------------------------------------
// Packed-f32x2 split-K GEMM (layer 1).  BM=64, BN=128, BK=16, 128 threads,
// per-thread 8x8 microtile as 32 f32x2 accumulators.  A stored DUPLICATED in
// smem so af pairs {a,a} and bf pairs {b0,b1} both load via LDS.128.
// gridDim.z = splits; writes fp32 partials to g_part[z*M*N].
// REMAP of B rows via c_WOFF (layer-1 feature concat skip).
// ---------------------------------------------------------------------------
__global__ void __launch_bounds__(128) gemm1_f32x2(
        const float* __restrict__ A, const float* __restrict__ Bm,
        int M, int N, int K, int Kc) {
    constexpr int BM = 64, BN = 128, BK = 16;

    __shared__ __align__(16) float As2[BK][2 * BM + 4];   // duplicated A
    __shared__ __align__(16) float Bs [BK][BN + 4];

    const int tid = threadIdx.x;
    const int tx = tid & 15;          // 16 -> columns
    const int ty = tid >> 4;          // 8  -> rows
    const int m0 = blockIdx.y * BM, n0 = blockIdx.x * BN;
    const int k0 = blockIdx.z * Kc;
    float* C = g_part + (size_t)blockIdx.z * M * N;

    // A loader: 2 float4 per thread (rows tid>>2 and +32, k nibble (tid&3)*4)
    const int a_r = tid >> 2;
    const int a_k = (tid & 3) << 2;
    // B loader: 4 float4 per thread (row tid>>3, cols ((tid&7)+8s)*4)
    const int b_k = tid >> 3;
    const int b_c = (tid & 7) << 2;

    float4 ra0, ra1, rb[4];

    {
        const float* Ap = A + (size_t)(m0 + a_r) * K + k0 + a_k;
        ra0 = *(const float4*)Ap;
        ra1 = *(const float4*)(Ap + (size_t)32 * K);
        int kg = k0 + b_k;
        int wr = c_WOFF[kg >> 9] + (kg & 511);
        const float* Bp = Bm + (size_t)wr * N + n0 + b_c;
        #pragma unroll
        for (int s = 0; s < 4; ++s) rb[s] = *(const float4*)(Bp + 32 * s);
    }

    unsigned long long acc2[8][4];
    #pragma unroll
    for (int i = 0; i < 8; ++i)
        #pragma unroll
        for (int j = 0; j < 4; ++j) acc2[i][j] = 0ULL;

    const int NT = Kc / BK;
    for (int t = 0; t < NT; ++t) {
        // A: store duplicated pairs
        {
            float2* d0 = (float2*)&As2[a_k][2 * a_r];
            float2* d1 = (float2*)&As2[a_k][2 * (a_r + 32)];
            const int str = (2 * BM + 4) / 2;          // row stride in float2
            d0[0 * str] = make_float2(ra0.x, ra0.x);
            d0[1 * str] = make_float2(ra0.y, ra0.y);
            d0[2 * str] = make_float2(ra0.z, ra0.z);
            d0[3 * str] = make_float2(ra0.w, ra0.w);
            d1[0 * str] = make_float2(ra1.x, ra1.x);
            d1[1 * str] = make_float2(ra1.y, ra1.y);
            d1[2 * str] = make_float2(ra1.z, ra1.z);
            d1[3 * str] = make_float2(ra1.w, ra1.w);
        }
        #pragma unroll
        for (int s = 0; s < 4; ++s)
            *(float4*)&Bs[b_k][b_c + 32 * s] = rb[s];
        __syncthreads();

        if (t + 1 < NT) {          // prefetch next K tile
            int kk0 = k0 + (t + 1) * BK;
            const float* Ap = A + (size_t)(m0 + a_r) * K + kk0 + a_k;
            ra0 = *(const float4*)Ap;
            ra1 = *(const float4*)(Ap + (size_t)32 * K);
            int kg = kk0 + b_k;
            int wr = c_WOFF[kg >> 9] + (kg & 511);
            const float* Bp = Bm + (size_t)wr * N + n0 + b_c;
            #pragma unroll
            for (int s = 0; s < 4; ++s) rb[s] = *(const float4*)(Bp + 32 * s);
        }

        #pragma unroll
        for (int kk = 0; kk < BK; ++kk) {
            const float* arow = &As2[kk][ty * 16];   // dup pairs of 8 rows
            const float* brow = &Bs[kk][tx * 8];     // 8 cols
            ulonglong2 a01 = *(const ulonglong2*)(arow + 0);
            ulonglong2 a23 = *(const ulonglong2*)(arow + 4);
            ulonglong2 a45 = *(const ulonglong2*)(arow + 8);
            ulonglong2 a67 = *(const ulonglong2*)(arow + 12);
            ulonglong2 b01 = *(const ulonglong2*)(brow + 0);
            ulonglong2 b23 = *(const ulonglong2*)(brow + 4);
            unsigned long long af[8] = {a01.x, a01.y, a23.x, a23.y,
                                        a45.x, a45.y, a67.x, a67.y};
            unsigned long long bf[4] = {b01.x, b01.y, b23.x, b23.y};
            #pragma unroll
            for (int i = 0; i < 8; ++i)
                #pragma unroll
                for (int j = 0; j < 4; ++j)
                    ffma2(acc2[i][j], af[i], bf[j]);
        }
        __syncthreads();
    }

    #pragma unroll
    for (int i = 0; i < 8; ++i) {
        int row = m0 + ty * 8 + i;
        unsigned long long* Cr =
            (unsigned long long*)(C + (size_t)row * N + n0 + tx * 8);
        #pragma unroll
        for (int j = 0; j < 4; ++j) Cr[j] = acc2[i][j];
    }
}

// ---------------------------------------------------------------------------
// Scalar split-K tiled fp32 GEMM (layers 2-3), 256 threads.
// ---------------------------------------------------------------------------
template<int BM, int BN, int TM, int TN>
__global__ void __launch_bounds__(256) gemm_split(
        const float* __restrict__ A, const float* __restrict__ Bm,
        int M, int N, int K, int Kc) {
    constexpr int BK = 16;
    constexpr int TX = BN / TN;
    constexpr int TY = BM / TM;
    static_assert(TX * TY == 256, "256 threads");
    static_assert(BN == 64, "B-tile loader assumes BN==64");

    __shared__ float As[BK][BM + 4];
    __shared__ float Bs[BK][BN + 4];

    const int tid = threadIdx.x;
    const int tx = tid % TX, ty = tid / TX;
    const int m0 = blockIdx.y * BM, n0 = blockIdx.x * BN;
    const int k0 = blockIdx.z * Kc;
    float* C = g_part + (size_t)blockIdx.z * M * N;

    const int  a_m   = tid >> 2;
    const int  a_k   = (tid & 3) << 2;
    const bool a_act = (BM * 4 >= 256) ? true : (tid < BM * 4);
    const int  b_k = tid >> 4;
    const int  b_n = (tid & 15) << 2;

    float4 ra = make_float4(0.f, 0.f, 0.f, 0.f);
    float4 rb;

    if (a_act) ra = *(const float4*)(A + (size_t)(m0 + a_m) * K + k0 + a_k);
    rb = *(const float4*)(Bm + (size_t)(k0 + b_k) * N + n0 + b_n);

    float acc[TM][TN];
    #pragma unroll
    for (int i = 0; i < TM; ++i)
        #pragma unroll
        for (int j = 0; j < TN; ++j) acc[i][j] = 0.f;

    const int NT = Kc / BK;
    for (int t = 0; t < NT; ++t) {
        if (a_act) {
            As[a_k + 0][a_m] = ra.x;
            As[a_k + 1][a_m] = ra.y;
            As[a_k + 2][a_m] = ra.z;
            As[a_k + 3][a_m] = ra.w;
        }
        *(float4*)&Bs[b_k][b_n] = rb;
        __syncthreads();

        if (t + 1 < NT) {
            int kk0 = k0 + (t + 1) * BK;
            if (a_act) ra = *(const float4*)(A + (size_t)(m0 + a_m) * K + kk0 + a_k);
            rb = *(const float4*)(Bm + (size_t)(kk0 + b_k) * N + n0 + b_n);
        }

        #pragma unroll
        for (int kk = 0; kk < BK; ++kk) {
            float af[TM], bf[TN];
            #pragma unroll
            for (int i = 0; i < TM; ++i) af[i] = As[kk][ty * TM + i];
            #pragma unroll
            for (int j = 0; j < TN; ++j) bf[j] = Bs[kk][tx * TN + j];
            #pragma unroll
            for (int i = 0; i < TM; ++i)
                #pragma unroll
                for (int j = 0; j < TN; ++j)
                    acc[i][j] = fmaf(af[i], bf[j], acc[i][j]);
        }
        __syncthreads();
    }

    #pragma unroll
    for (int i = 0; i < TM; ++i) {
        int row = m0 + ty * TM + i;
        #pragma unroll
        for (int j = 0; j < TN; ++j)
            C[(size_t)row * N + n0 + tx * TN + j] = acc[i][j];
    }
}

// ---------------------------------------------------------------------------
// out = act(sum_z part[z] + bias [+ C0]); fixed order -> deterministic.
// ---------------------------------------------------------------------------
template<int S, bool RELU, bool ADDC0>
__global__ void combine_k(const float* __restrict__ bias,
                          const float* __restrict__ C0,
                          float* __restrict__ out, int MN4, int N4) {
    int i = blockIdx.x * blockDim.x + threadIdx.x;
    if (i >= MN4) return;
    const float4* p = (const float4*)g_part;
    float4 v = __ldg(&((const float4*)bias)[i % N4]);
    #pragma unroll
    for (int s = 0; s < S; ++s) {
        float4 q = p[(size_t)s * MN4 + i];
        v.x += q.x; v.y += q.y; v.z += q.z; v.w += q.w;
    }
    if (ADDC0) {
        float4 c = ((const float4*)C0)[i];
        v.x += c.x; v.y += c.y; v.z += c.z; v.w += c.w;
    }
    if (RELU) {
        v.x = fmaxf(v.x, 0.f); v.y = fmaxf(v.y, 0.f);
        v.z = fmaxf(v.z, 0.f); v.w = fmaxf(v.w, 0.f);
    }
    ((float4*)out)[i] = v;
}

// ---------------------------------------------------------------------------
extern "C" void kernel_launch(void* const* d_in, const int* in_sizes, int n_in,
                              void* d_out, int out_size) {
    (void)in_sizes; (void)n_in; (void)out_size;

    const float* T_name        = (const float*)d_in[0];
    const float* T_collab      = (const float*)d_in[1];
    const float* T_track_can   = (const float*)d_in[2];
    const float* T_artist_name = (const float*)d_in[3];
    const float* T_track_uri   = (const float*)d_in[4];
    const float* T_track_name  = (const float*)d_in[5];
    const float* T_dur         = (const float*)d_in[6];
    const float* T_album       = (const float*)d_in[7];
    const float* T_apop        = (const float*)d_in[8];
    const float* T_afol        = (const float*)d_in[9];
    const float* T_tpop        = (const float*)d_in[10];
    const float* T_genres      = (const float*)d_in[11];
    const float* W1 = (const float*)d_in[12];
    const float* b1 = (const float*)d_in[13];
    const float* W2 = (const float*)d_in[14];
    const float* b2 = (const float*)d_in[15];
    const float* W3 = (const float*)d_in[16];
    const float* b3 = (const float*)d_in[17];
    const int* id_name         = (const int*)d_in[18];
    const int* id_collab       = (const int*)d_in[19];
    const int* id_track_can    = (const int*)d_in[20];
    const int* seq_artist_name = (const int*)d_in[21];
    const int* seq_track_uri   = (const int*)d_in[22];
    const int* seq_track_name  = (const int*)d_in[23];
    const int* seq_dur         = (const int*)d_in[24];
    const int* seq_album       = (const int*)d_in[25];
    const int* seq_apop        = (const int*)d_in[26];
    const int* seq_afol        = (const int*)d_in[27];
    const int* seq_tpop        = (const int*)d_in[28];
    const int* seq_genres      = (const int*)d_in[29];

    float *Xp, *Y0, *H1, *H2;
    cudaGetSymbolAddress((void**)&Xp, g_X);
    cudaGetSymbolAddress((void**)&Y0, g_Y0);
    cudaGetSymbolAddress((void**)&H1, g_H1);
    cudaGetSymbolAddress((void**)&H2, g_H2);

    BigArgs ba;
    ba.tbl[0] = T_name;        ba.idx[0] = id_name;
    ba.tbl[1] = T_track_can;   ba.idx[1] = id_track_can;
    ba.tbl[2] = T_artist_name; ba.idx[2] = seq_artist_name;
    ba.tbl[3] = T_track_uri;   ba.idx[3] = seq_track_uri;
    ba.tbl[4] = T_track_name;  ba.idx[4] = seq_track_name;
    ba.tbl[5] = T_album;       ba.idx[5] = seq_album;
    ba.tbl[6] = T_genres;      ba.idx[6] = seq_genres;

    big_pool<<<dim3(NB, 7), 128>>>(ba);
    precompute_P<<<88, 512>>>(T_collab, T_dur, T_apop, T_afol, T_tpop, W1);
    small_pool<<<NB, 128>>>(id_collab, seq_dur, seq_apop, seq_afol, seq_tpop);

    // layer 1: [1024,3584] @ W1(remap); packed f32x2; split-K=4 -> 256 blocks
    gemm1_f32x2<<<dim3(512 / 128, NB / 64, 4), 128>>>(
        Xp, W1, NB, 512, KBIG, KBIG / 4);
    combine_k<4, true, true><<<(NB * 512 / 4 + 255) / 256, 256>>>(
        b1, Y0, H1, NB * 512 / 4, 512 / 4);

    // layer 2: [1024,512] @ W2; split-K=2 (Kc=256) -> 128 blocks
    gemm_split<64, 64, 4, 4><<<dim3(256 / 64, NB / 64, 2), 256>>>(
        H1, W2, NB, 256, 512, 256);
    combine_k<2, true, false><<<(NB * 256 / 4 + 255) / 256, 256>>>(
        b2, nullptr, H2, NB * 256 / 4, 256 / 4);

    // layer 3: [1024,256] @ W3; split-K=4 (Kc=64) -> 128 blocks
    gemm_split<64, 64, 4, 4><<<dim3(128 / 64, NB / 64, 4), 256>>>(
        H2, W3, NB, 128, 256, 64);
    combine_k<4, false, false><<<(NB * 128 / 4 + 255) / 256, 256>>>(
        b3, nullptr, (float*)d_out, NB * 128 / 4, 128 / 4);
}

// round 11
// speedup vs baseline: 1.0060x; 1.0060x over previous
#include <cuda_runtime.h>
#include <cstdint>

// ---------------------------------------------------------------------------
// Playlist model:
//   12 embedding towers (3 single-lookup, 9 mean-pooled over L=100)
//   -> concat [B, 12*512] -> Dense(512) relu -> Dense(256) relu -> Dense(128)
//
// R11 structure:
//   * Small tables folded through W1 by linearity (P = T_small @ W1_slice,
//     88x512), bucket features via 21-bin histogram -> Y0 [B,512].
//   * FUSED persistent kernel overlaps the DRAM-bound big-feature pooling
//     with the fma-bound GEMM1 (K=3584, split-K per feature z in [0,7)).
//     Work items come off a global ticket queue, interleaved
//     [copies, gemm z0, gemm z1, (pool f, gemm z=f) for f=2..6]; gemm tiles
//     spin on per-(feature, 64-row-block) completion counters
//     (release = threadfence+atomicAdd, acquire = atomic read+threadfence).
//     Deadlock-free: an item only waits on strictly-earlier queue items,
//     which are held by running blocks, and producers never wait.
//   * Split-K partials + combine kernel (fixed-order sum => deterministic).
// ---------------------------------------------------------------------------

#define NB   1024
#define NL   100
#define KBIG 3584          // 7 * 512

__device__ float g_X   [NB * KBIG];
__device__ float g_Y0  [NB * 512];
__device__ float g_P   [88 * 512];
__device__ float g_H1  [NB * 512];
__device__ float g_H2  [NB * 256];
__device__ float g_part[7 * NB * 512];     // split-K partials (7 x 1024 x 512)

__device__ int g_ticket;
__device__ int g_cnt[7][16];               // per (feature, 64-row block)

// W1 row offsets for the 7 big features in X-column order:
// name, track_can, artist_name, track_uri, track_name, album, genres
__constant__ int c_WOFF[7] = {0, 1024, 1536, 2048, 2560, 3584, 5632};

// Work queue layout
#define IT_COPY   64                      // 64 copy items (16 b x 2 features)
#define IT_GEMM   128                     // gemm tiles per z (16 mblk x 8 nblk)
#define IT_POOL   128                     // pool items per f (8 b each)
#define N_ITEMS   (IT_COPY + 2 * IT_GEMM + 5 * (IT_POOL + IT_GEMM))   // 1600

// ---------------------------------------------------------------------------
__global__ void init_mega() {
    if (threadIdx.x == 0) g_ticket = 0;
    if (threadIdx.x < 112) ((int*)g_cnt)[threadIdx.x] = 0;
}

// ---------------------------------------------------------------------------
__global__ void precompute_P(const float* __restrict__ T_collab,
                             const float* __restrict__ T_dur,
                             const float* __restrict__ T_apop,
                             const float* __restrict__ T_afol,
                             const float* __restrict__ T_tpop,
                             const float* __restrict__ W1) {
    __shared__ float s_t[512];
    int r = blockIdx.x;
    const float* T; int row; int off;
    if (r < 4)       { T = T_collab; row = r;      off = 512;  }
    else if (r < 25) { T = T_dur;    row = r - 4;  off = 3072; }
    else if (r < 46) { T = T_apop;   row = r - 25; off = 4096; }
    else if (r < 67) { T = T_afol;   row = r - 46; off = 4608; }
    else             { T = T_tpop;   row = r - 67; off = 5120; }
    int n = threadIdx.x;                       // 512 threads
    s_t[n] = T[row * 512 + n];
    __syncthreads();
    float acc = 0.0f;
    const float* w = W1 + (size_t)off * 512 + n;
    #pragma unroll 8
    for (int k = 0; k < 512; ++k)
        acc = fmaf(s_t[k], w[(size_t)k * 512], acc);
    g_P[r * 512 + n] = acc;
}

// ---------------------------------------------------------------------------
__global__ void small_pool(const int* __restrict__ id_collab,
                           const int* __restrict__ seq_dur,
                           const int* __restrict__ seq_apop,
                           const int* __restrict__ seq_afol,
                           const int* __restrict__ seq_tpop) {
    __shared__ int cnt[21];
    const int b = blockIdx.x, t = threadIdx.x;     // 128 threads, float4 lanes
    const float4* P4 = (const float4*)g_P;

    const int idc = id_collab[b];
    float4 acc = __ldg(&P4[(size_t)idc * 128 + t]);
    float4 ab  = make_float4(0.f, 0.f, 0.f, 0.f);

    const int* seqs[4]  = {seq_dur, seq_apop, seq_afol, seq_tpop};
    const int  pbase[4] = {4, 25, 46, 67};

    for (int j = 0; j < 4; ++j) {
        if (t < 21) cnt[t] = 0;
        __syncthreads();
        if (t < NL) atomicAdd(&cnt[seqs[j][b * NL + t]], 1);
        __syncthreads();
        #pragma unroll
        for (int v = 0; v < 21; ++v) {
            int c = cnt[v];
            if (c) {
                float fc = (float)c;
                float4 p = __ldg(&P4[(size_t)(pbase[j] + v) * 128 + t]);
                ab.x = fmaf(fc, p.x, ab.x);
                ab.y = fmaf(fc, p.y, ab.y);
                ab.z = fmaf(fc, p.z, ab.z);
                ab.w = fmaf(fc, p.w, ab.w);
            }
        }
        __syncthreads();
    }
    float4 o;
    o.x = acc.x + 0.01f * ab.x;
    o.y = acc.y + 0.01f * ab.y;
    o.z = acc.z + 0.01f * ab.z;
    o.w = acc.w + 0.01f * ab.w;
    ((float4*)g_Y0)[(size_t)b * 128 + t] = o;
}

// ---------------------------------------------------------------------------
// Fused persistent pooling + GEMM1 kernel.
// ---------------------------------------------------------------------------
struct MegaArgs {
    const float* tbl[7];    // tables in X feature order
    const int*   idx[7];    // f<2: [B] ids; f>=2: [B,L] sequences
    const float* W1;
};

__global__ void __launch_bounds__(256) mega(MegaArgs a) {
    __shared__ __align__(16) float smem[2176];   // gemm: As(16x68)+Bs(16x68)
    __shared__ int s_item;

    const int tid = threadIdx.x;
    float4* X4 = (float4*)g_X;

    for (;;) {
        if (tid == 0) s_item = atomicAdd(&g_ticket, 1);
        __syncthreads();
        const int it = s_item;
        if (it >= N_ITEMS) break;   // uniform exit: all threads read same it

        // ---- decode item ----
        int kind;      // 0=copy, 1=pool, 2=gemm
        int f = 0, sub = 0, z = 0, r = 0;
        if (it < IT_COPY) { kind = 0; sub = it; }
        else if (it < IT_COPY + IT_GEMM)     { kind = 2; z = 0; r = it - IT_COPY; }
        else if (it < IT_COPY + 2 * IT_GEMM) { kind = 2; z = 1; r = it - IT_COPY - IT_GEMM; }
        else {
            int t2 = it - (IT_COPY + 2 * IT_GEMM);
            int grp = t2 / (IT_POOL + IT_GEMM);      // 0..4 -> feature 2..6
            int rem = t2 % (IT_POOL + IT_GEMM);
            if (rem < IT_POOL) { kind = 1; f = 2 + grp; sub = rem; }
            else               { kind = 2; z = 2 + grp; r = rem - IT_POOL; }
        }

        if (kind == 0) {
            // ---- copy item: 16 b's x 2 single-lookup features ----
            const int b0 = sub * 16;
            const int feat = tid >> 7;           // 0 or 1
            const int col  = tid & 127;
            const float4* T = (const float4*)a.tbl[feat];
            #pragma unroll 4
            for (int k = 0; k < 16; ++k) {
                int b  = b0 + k;
                int id = a.idx[feat][b];
                X4[(size_t)b * 896 + feat * 128 + col] =
                    __ldg(&T[(size_t)id * 128 + col]);
            }
            __threadfence();
            __syncthreads();
            if (tid == 0) {
                atomicAdd(&g_cnt[0][sub >> 2], 1);
                atomicAdd(&g_cnt[1][sub >> 2], 1);
            }
        } else if (kind == 1) {
            // ---- pool item: 8 b's of feature f, mean over L=100 ----
            int* sidx = (int*)smem;              // [2][128]
            const int half = tid >> 7, lt = tid & 127;
            const int b0 = sub * 8;
            const float4* T = (const float4*)a.tbl[f];
            const int* seq = a.idx[f];
            for (int p = 0; p < 4; ++p) {
                int b = b0 + p * 2 + half;
                if (lt < NL) sidx[half * 128 + lt] = seq[b * NL + lt];
                __syncthreads();
                float4 acc = make_float4(0.f, 0.f, 0.f, 0.f);
                #pragma unroll 10
                for (int l = 0; l < NL; ++l) {
                    float4 v = __ldg(&T[(size_t)sidx[half * 128 + l] * 128 + lt]);
                    acc.x += v.x; acc.y += v.y; acc.z += v.z; acc.w += v.w;
                }
                acc.x *= 0.01f; acc.y *= 0.01f; acc.z *= 0.01f; acc.w *= 0.01f;
                X4[(size_t)b * 896 + f * 128 + lt] = acc;
                __syncthreads();
            }
            __threadfence();
            if (tid == 0) atomicAdd(&g_cnt[f][sub >> 3], 1);
            __syncthreads();
        } else {
            // ---- gemm tile: 64x64, Kc=512 (feature z), split-K partial ----
            const int mblk = r >> 3, nblk = r & 7;
            const int tgt = (z < 2) ? 4 : 8;
            if (tid == 0) {
                while (atomicAdd(&g_cnt[z][mblk], 0) < tgt) __nanosleep(200);
                __threadfence();
            }
            __syncthreads();

            float (*As)[68] = (float(*)[68])smem;
            float (*Bs)[68] = (float(*)[68])(smem + 16 * 68);

            const int tx = tid & 15, ty = tid >> 4;
            const int m0 = mblk * 64, n0 = nblk * 64;
            const int k0 = z * 512;
            float* C = g_part + (size_t)z * NB * 512;

            const int a_m = tid >> 2;
            const int a_k = (tid & 3) << 2;
            const int b_k = tid >> 4;
            const int b_n = (tid & 15) << 2;

            const float* A = g_X;
            const float* Bm = a.W1;

            float4 ra = *(const float4*)(A + (size_t)(m0 + a_m) * KBIG + k0 + a_k);
            float4 rb;
            {
                int kg = k0 + b_k;
                int wr = c_WOFF[kg >> 9] + (kg & 511);
                rb = *(const float4*)(Bm + (size_t)wr * 512 + n0 + b_n);
            }

            float acc[4][4];
            #pragma unroll
            for (int i = 0; i < 4; ++i)
                #pragma unroll
                for (int j = 0; j < 4; ++j) acc[i][j] = 0.f;

            const int NT = 512 / 16;
            for (int t = 0; t < NT; ++t) {
                As[a_k + 0][a_m] = ra.x;
                As[a_k + 1][a_m] = ra.y;
                As[a_k + 2][a_m] = ra.z;
                As[a_k + 3][a_m] = ra.w;
                *(float4*)&Bs[b_k][b_n] = rb;
                __syncthreads();

                if (t + 1 < NT) {
                    int kk0 = k0 + (t + 1) * 16;
                    ra = *(const float4*)(A + (size_t)(m0 + a_m) * KBIG + kk0 + a_k);
                    int kg = kk0 + b_k;
                    int wr = c_WOFF[kg >> 9] + (kg & 511);
                    rb = *(const float4*)(Bm + (size_t)wr * 512 + n0 + b_n);
                }

                #pragma unroll
                for (int kk = 0; kk < 16; ++kk) {
                    float af[4], bf[4];
                    #pragma unroll
                    for (int i = 0; i < 4; ++i) af[i] = As[kk][ty * 4 + i];
                    #pragma unroll
                    for (int j = 0; j < 4; ++j) bf[j] = Bs[kk][tx * 4 + j];
                    #pragma unroll
                    for (int i = 0; i < 4; ++i)
                        #pragma unroll
                        for (int j = 0; j < 4; ++j)
                            acc[i][j] = fmaf(af[i], bf[j], acc[i][j]);
                }
                __syncthreads();
            }

            #pragma unroll
            for (int i = 0; i < 4; ++i) {
                int row = m0 + ty * 4 + i;
                #pragma unroll
                for (int j = 0; j < 4; ++j)
                    C[(size_t)row * 512 + n0 + tx * 4 + j] = acc[i][j];
            }
            __syncthreads();
        }
    }
}

// ---------------------------------------------------------------------------
// Scalar split-K tiled fp32 GEMM (layers 2-3), 256 threads. (R9-proven)
// ---------------------------------------------------------------------------
template<int BM, int BN, int TM, int TN>
__global__ void __launch_bounds__(256) gemm_split(
        const float* __restrict__ A, const float* __restrict__ Bm,
        int M, int N, int K, int Kc) {
    constexpr int BK = 16;
    constexpr int TX = BN / TN;
    constexpr int TY = BM / TM;
    static_assert(TX * TY == 256, "256 threads");
    static_assert(BN == 64, "B-tile loader assumes BN==64");

    __shared__ float As[BK][BM + 4];
    __shared__ float Bs[BK][BN + 4];

    const int tid = threadIdx.x;
    const int tx = tid % TX, ty = tid / TX;
    const int m0 = blockIdx.y * BM, n0 = blockIdx.x * BN;
    const int k0 = blockIdx.z * Kc;
    float* C = g_part + (size_t)blockIdx.z * M * N;

    const int  a_m   = tid >> 2;
    const int  a_k   = (tid & 3) << 2;
    const bool a_act = (BM * 4 >= 256) ? true : (tid < BM * 4);
    const int  b_k = tid >> 4;
    const int  b_n = (tid & 15) << 2;

    float4 ra = make_float4(0.f, 0.f, 0.f, 0.f);
    float4 rb;

    if (a_act) ra = *(const float4*)(A + (size_t)(m0 + a_m) * K + k0 + a_k);
    rb = *(const float4*)(Bm + (size_t)(k0 + b_k) * N + n0 + b_n);

    float acc[TM][TN];
    #pragma unroll
    for (int i = 0; i < TM; ++i)
        #pragma unroll
        for (int j = 0; j < TN; ++j) acc[i][j] = 0.f;

    const int NT = Kc / BK;
    for (int t = 0; t < NT; ++t) {
        if (a_act) {
            As[a_k + 0][a_m] = ra.x;
            As[a_k + 1][a_m] = ra.y;
            As[a_k + 2][a_m] = ra.z;
            As[a_k + 3][a_m] = ra.w;
        }
        *(float4*)&Bs[b_k][b_n] = rb;
        __syncthreads();

        if (t + 1 < NT) {
            int kk0 = k0 + (t + 1) * BK;
            if (a_act) ra = *(const float4*)(A + (size_t)(m0 + a_m) * K + kk0 + a_k);
            rb = *(const float4*)(Bm + (size_t)(kk0 + b_k) * N + n0 + b_n);
        }

        #pragma unroll
        for (int kk = 0; kk < BK; ++kk) {
            float af[TM], bf[TN];
            #pragma unroll
            for (int i = 0; i < TM; ++i) af[i] = As[kk][ty * TM + i];
            #pragma unroll
            for (int j = 0; j < TN; ++j) bf[j] = Bs[kk][tx * TN + j];
            #pragma unroll
            for (int i = 0; i < TM; ++i)
                #pragma unroll
                for (int j = 0; j < TN; ++j)
                    acc[i][j] = fmaf(af[i], bf[j], acc[i][j]);
        }
        __syncthreads();
    }

    #pragma unroll
    for (int i = 0; i < TM; ++i) {
        int row = m0 + ty * TM + i;
        #pragma unroll
        for (int j = 0; j < TN; ++j)
            C[(size_t)row * N + n0 + tx * TN + j] = acc[i][j];
    }
}

// ---------------------------------------------------------------------------
// out = act(sum_z part[z] + bias [+ C0]); fixed order -> deterministic.
// ---------------------------------------------------------------------------
template<int S, bool RELU, bool ADDC0>
__global__ void combine_k(const float* __restrict__ bias,
                          const float* __restrict__ C0,
                          float* __restrict__ out, int MN4, int N4) {
    int i = blockIdx.x * blockDim.x + threadIdx.x;
    if (i >= MN4) return;
    const float4* p = (const float4*)g_part;
    float4 v = __ldg(&((const float4*)bias)[i % N4]);
    #pragma unroll
    for (int s = 0; s < S; ++s) {
        float4 q = p[(size_t)s * MN4 + i];
        v.x += q.x; v.y += q.y; v.z += q.z; v.w += q.w;
    }
    if (ADDC0) {
        float4 c = ((const float4*)C0)[i];
        v.x += c.x; v.y += c.y; v.z += c.z; v.w += c.w;
    }
    if (RELU) {
        v.x = fmaxf(v.x, 0.f); v.y = fmaxf(v.y, 0.f);
        v.z = fmaxf(v.z, 0.f); v.w = fmaxf(v.w, 0.f);
    }
    ((float4*)out)[i] = v;
}

// ---------------------------------------------------------------------------
extern "C" void kernel_launch(void* const* d_in, const int* in_sizes, int n_in,
                              void* d_out, int out_size) {
    (void)in_sizes; (void)n_in; (void)out_size;

    const float* T_name        = (const float*)d_in[0];
    const float* T_collab      = (const float*)d_in[1];
    const float* T_track_can   = (const float*)d_in[2];
    const float* T_artist_name = (const float*)d_in[3];
    const float* T_track_uri   = (const float*)d_in[4];
    const float* T_track_name  = (const float*)d_in[5];
    const float* T_dur         = (const float*)d_in[6];
    const float* T_album       = (const float*)d_in[7];
    const float* T_apop        = (const float*)d_in[8];
    const float* T_afol        = (const float*)d_in[9];
    const float* T_tpop        = (const float*)d_in[10];
    const float* T_genres      = (const float*)d_in[11];
    const float* W1 = (const float*)d_in[12];
    const float* b1 = (const float*)d_in[13];
    const float* W2 = (const float*)d_in[14];
    const float* b2 = (const float*)d_in[15];
    const float* W3 = (const float*)d_in[16];
    const float* b3 = (const float*)d_in[17];
    const int* id_name         = (const int*)d_in[18];
    const int* id_collab       = (const int*)d_in[19];
    const int* id_track_can    = (const int*)d_in[20];
    const int* seq_artist_name = (const int*)d_in[21];
    const int* seq_track_uri   = (const int*)d_in[22];
    const int* seq_track_name  = (const int*)d_in[23];
    const int* seq_dur         = (const int*)d_in[24];
    const int* seq_album       = (const int*)d_in[25];
    const int* seq_apop        = (const int*)d_in[26];
    const int* seq_afol        = (const int*)d_in[27];
    const int* seq_tpop        = (const int*)d_in[28];
    const int* seq_genres      = (const int*)d_in[29];

    float *Y0, *H1, *H2;
    cudaGetSymbolAddress((void**)&Y0, g_Y0);
    cudaGetSymbolAddress((void**)&H1, g_H1);
    cudaGetSymbolAddress((void**)&H2, g_H2);

    MegaArgs ma;
    ma.tbl[0] = T_name;        ma.idx[0] = id_name;
    ma.tbl[1] = T_track_can;   ma.idx[1] = id_track_can;
    ma.tbl[2] = T_artist_name; ma.idx[2] = seq_artist_name;
    ma.tbl[3] = T_track_uri;   ma.idx[3] = seq_track_uri;
    ma.tbl[4] = T_track_name;  ma.idx[4] = seq_track_name;
    ma.tbl[5] = T_album;       ma.idx[5] = seq_album;
    ma.tbl[6] = T_genres;      ma.idx[6] = seq_genres;
    ma.W1 = W1;

    // independent small-feature fold (cheap, serial at front)
    precompute_P<<<88, 512>>>(T_collab, T_dur, T_apop, T_afol, T_tpop, W1);
    small_pool<<<NB, 128>>>(id_collab, seq_dur, seq_apop, seq_afol, seq_tpop);

    // fused pooling + GEMM1 (persistent, ticket queue)
    init_mega<<<1, 128>>>();
    mega<<<592, 256>>>(ma);

    // H1 = relu(sum_z part[z] + Y0 + b1)
    combine_k<7, true, true><<<(NB * 512 / 4 + 255) / 256, 256>>>(
        b1, Y0, H1, NB * 512 / 4, 512 / 4);

    // layer 2: [1024,512] @ W2; split-K=2 (Kc=256) -> 256 blocks
    gemm_split<32, 64, 2, 4><<<dim3(256 / 64, NB / 32, 2), 256>>>(
        H1, W2, NB, 256, 512, 256);
    combine_k<2, true, false><<<(NB * 256 / 4 + 255) / 256, 256>>>(
        b2, nullptr, H2, NB * 256 / 4, 256 / 4);

    // layer 3: [1024,256] @ W3; split-K=4 (Kc=64) -> 256 blocks
    gemm_split<32, 64, 2, 4><<<dim3(128 / 64, NB / 32, 4), 256>>>(
        H2, W3, NB, 128, 256, 64);
    combine_k<4, false, false><<<(NB * 128 / 4 + 255) / 256, 256>>>(
        b3, nullptr, (float*)d_out, NB * 128 / 4, 128 / 4);
}

// round 12
// speedup vs baseline: 1.0228x; 1.0167x over previous
#include <cuda_runtime.h>
#include <cstdint>

// ---------------------------------------------------------------------------
// Playlist model:
//   12 embedding towers (3 single-lookup, 9 mean-pooled over L=100)
//   -> concat [B, 12*512] -> Dense(512) relu -> Dense(256) relu -> Dense(128)
//
// R12 structure:
//   * Small tables folded through W1 by linearity -> Y0 [B,512] (g_P 88x512).
//   * FUSED persistent kernel overlaps DRAM-bound pooling with fma-bound
//     GEMM1 (split-K per feature). R12 fixes the R11 schedule: pool and gemm
//     tickets are interleaved 5:7 throughout (pool f-major, gemm z-major),
//     so ~half the resident blocks gather while the rest compute, instead of
//     features trickling serially. Pool items cover 8 rows with one index
//     stage and no inner syncs (max MLP).
//   * Deadlock-free: gemm tiles wait only on strictly-earlier tickets held by
//     resident blocks; producers never wait. Fixed-order math (deterministic).
// ---------------------------------------------------------------------------

#define NB   1024
#define NL   100
#define KBIG 3584          // 7 * 512

__device__ float g_X   [NB * KBIG];
__device__ float g_Y0  [NB * 512];
__device__ float g_P   [88 * 512];
__device__ float g_H1  [NB * 512];
__device__ float g_H2  [NB * 256];
__device__ float g_part[7 * NB * 512];     // split-K partials (7 x 1024 x 512)

__device__ int g_ticket;
__device__ int g_cnt[7][16];               // per (feature, 64-row block)

// W1 row offsets for the 7 big features in X-column order:
// name, track_can, artist_name, track_uri, track_name, album, genres
__constant__ int c_WOFF[7] = {0, 1024, 1536, 2048, 2560, 3584, 5632};

// Work queue: 64 copy items, then 128 groups of [5 pool, 7 gemm].
// pool stream: 5 features x 128 items (8 b each), f-major.
// gemm stream: 7 z x 128 tiles (64x64), z-major, mblk-major within z.
#define IT_COPY   64
#define N_ITEMS   (IT_COPY + 128 * 12)    // 1600

// ---------------------------------------------------------------------------
__global__ void init_mega() {
    if (threadIdx.x == 0) g_ticket = 0;
    if (threadIdx.x < 112) ((int*)g_cnt)[threadIdx.x] = 0;
}

// ---------------------------------------------------------------------------
__global__ void precompute_P(const float* __restrict__ T_collab,
                             const float* __restrict__ T_dur,
                             const float* __restrict__ T_apop,
                             const float* __restrict__ T_afol,
                             const float* __restrict__ T_tpop,
                             const float* __restrict__ W1) {
    __shared__ float s_t[512];
    int r = blockIdx.x;
    const float* T; int row; int off;
    if (r < 4)       { T = T_collab; row = r;      off = 512;  }
    else if (r < 25) { T = T_dur;    row = r - 4;  off = 3072; }
    else if (r < 46) { T = T_apop;   row = r - 25; off = 4096; }
    else if (r < 67) { T = T_afol;   row = r - 46; off = 4608; }
    else             { T = T_tpop;   row = r - 67; off = 5120; }
    int n = threadIdx.x;                       // 512 threads
    s_t[n] = T[row * 512 + n];
    __syncthreads();
    float acc = 0.0f;
    const float* w = W1 + (size_t)off * 512 + n;
    #pragma unroll 8
    for (int k = 0; k < 512; ++k)
        acc = fmaf(s_t[k], w[(size_t)k * 512], acc);
    g_P[r * 512 + n] = acc;
}

// ---------------------------------------------------------------------------
__global__ void small_pool(const int* __restrict__ id_collab,
                           const int* __restrict__ seq_dur,
                           const int* __restrict__ seq_apop,
                           const int* __restrict__ seq_afol,
                           const int* __restrict__ seq_tpop) {
    __shared__ int cnt[21];
    const int b = blockIdx.x, t = threadIdx.x;     // 128 threads, float4 lanes
    const float4* P4 = (const float4*)g_P;

    const int idc = id_collab[b];
    float4 acc = __ldg(&P4[(size_t)idc * 128 + t]);
    float4 ab  = make_float4(0.f, 0.f, 0.f, 0.f);

    const int* seqs[4]  = {seq_dur, seq_apop, seq_afol, seq_tpop};
    const int  pbase[4] = {4, 25, 46, 67};

    for (int j = 0; j < 4; ++j) {
        if (t < 21) cnt[t] = 0;
        __syncthreads();
        if (t < NL) atomicAdd(&cnt[seqs[j][b * NL + t]], 1);
        __syncthreads();
        #pragma unroll
        for (int v = 0; v < 21; ++v) {
            int c = cnt[v];
            if (c) {
                float fc = (float)c;
                float4 p = __ldg(&P4[(size_t)(pbase[j] + v) * 128 + t]);
                ab.x = fmaf(fc, p.x, ab.x);
                ab.y = fmaf(fc, p.y, ab.y);
                ab.z = fmaf(fc, p.z, ab.z);
                ab.w = fmaf(fc, p.w, ab.w);
            }
        }
        __syncthreads();
    }
    float4 o;
    o.x = acc.x + 0.01f * ab.x;
    o.y = acc.y + 0.01f * ab.y;
    o.z = acc.z + 0.01f * ab.z;
    o.w = acc.w + 0.01f * ab.w;
    ((float4*)g_Y0)[(size_t)b * 128 + t] = o;
}

// ---------------------------------------------------------------------------
// Fused persistent pooling + GEMM1 kernel.
// ---------------------------------------------------------------------------
struct MegaArgs {
    const float* tbl[7];    // tables in X feature order
    const int*   idx[7];    // f<2: [B] ids; f>=2: [B,L] sequences
    const float* W1;
};

__global__ void __launch_bounds__(256) mega(MegaArgs a) {
    __shared__ __align__(16) float smem[2176];   // gemm: As(16x68)+Bs(16x68)
    __shared__ int s_item;

    const int tid = threadIdx.x;
    float4* X4 = (float4*)g_X;

    for (;;) {
        if (tid == 0) s_item = atomicAdd(&g_ticket, 1);
        __syncthreads();
        const int it = s_item;
        if (it >= N_ITEMS) break;   // uniform exit: all threads read same it

        // ---- decode item: interleaved [5 pool, 7 gemm] groups ----
        int kind;      // 0=copy, 1=pool, 2=gemm
        int f = 0, sub = 0, z = 0, r = 0;
        if (it < IT_COPY) { kind = 0; sub = it; }
        else {
            int t2 = it - IT_COPY;
            int g = t2 / 12, l = t2 - g * 12;
            if (l < 5) { int p = g * 5 + l;       kind = 1; f = 2 + (p >> 7); sub = p & 127; }
            else       { int q = g * 7 + (l - 5); kind = 2; z = q >> 7;       r = q & 127; }
        }

        if (kind == 0) {
            // ---- copy item: 16 b's x 2 single-lookup features ----
            const int b0 = sub * 16;
            const int feat = tid >> 7;           // 0 or 1
            const int col  = tid & 127;
            const float4* T = (const float4*)a.tbl[feat];
            #pragma unroll 4
            for (int k = 0; k < 16; ++k) {
                int b  = b0 + k;
                int id = a.idx[feat][b];
                X4[(size_t)b * 896 + feat * 128 + col] =
                    __ldg(&T[(size_t)id * 128 + col]);
            }
            __threadfence();
            __syncthreads();
            if (tid == 0) {
                atomicAdd(&g_cnt[0][sub >> 2], 1);
                atomicAdd(&g_cnt[1][sub >> 2], 1);
            }
        } else if (kind == 1) {
            // ---- pool item: 8 b's of feature f, mean over L=100 ----
            int* sidx = (int*)smem;              // 800 indices
            const int b0 = sub * 8;
            const int* seq = a.idx[f] + b0 * NL;
            for (int i = tid; i < 8 * NL; i += 256) sidx[i] = seq[i];
            __syncthreads();

            const int half = tid >> 7, lt = tid & 127;
            const float4* T = (const float4*)a.tbl[f];
            #pragma unroll
            for (int p = 0; p < 4; ++p) {
                const int bb = p * 2 + half;     // 0..7
                const int* sx = sidx + bb * NL;
                float4 acc = make_float4(0.f, 0.f, 0.f, 0.f);
                #pragma unroll 10
                for (int l = 0; l < NL; ++l) {
                    float4 v = __ldg(&T[(size_t)sx[l] * 128 + lt]);
                    acc.x += v.x; acc.y += v.y; acc.z += v.z; acc.w += v.w;
                }
                acc.x *= 0.01f; acc.y *= 0.01f; acc.z *= 0.01f; acc.w *= 0.01f;
                X4[(size_t)(b0 + bb) * 896 + f * 128 + lt] = acc;
            }
            __threadfence();
            __syncthreads();
            if (tid == 0) atomicAdd(&g_cnt[f][sub >> 3], 1);
        } else {
            // ---- gemm tile: 64x64, Kc=512 (feature z), split-K partial ----
            const int mblk = r >> 3, nblk = r & 7;
            const int tgt = (z < 2) ? 4 : 8;
            if (tid == 0) {
                while (atomicAdd(&g_cnt[z][mblk], 0) < tgt) __nanosleep(200);
                __threadfence();
            }
            __syncthreads();

            float (*As)[68] = (float(*)[68])smem;
            float (*Bs)[68] = (float(*)[68])(smem + 16 * 68);

            const int tx = tid & 15, ty = tid >> 4;
            const int m0 = mblk * 64, n0 = nblk * 64;
            const int k0 = z * 512;
            float* C = g_part + (size_t)z * NB * 512;

            const int a_m = tid >> 2;
            const int a_k = (tid & 3) << 2;
            const int b_k = tid >> 4;
            const int b_n = (tid & 15) << 2;

            const float* A = g_X;
            const float* Bm = a.W1;

            float4 ra = *(const float4*)(A + (size_t)(m0 + a_m) * KBIG + k0 + a_k);
            float4 rb;
            {
                int kg = k0 + b_k;
                int wr = c_WOFF[kg >> 9] + (kg & 511);
                rb = *(const float4*)(Bm + (size_t)wr * 512 + n0 + b_n);
            }

            float acc[4][4];
            #pragma unroll
            for (int i = 0; i < 4; ++i)
                #pragma unroll
                for (int j = 0; j < 4; ++j) acc[i][j] = 0.f;

            const int NT = 512 / 16;
            for (int t = 0; t < NT; ++t) {
                As[a_k + 0][a_m] = ra.x;
                As[a_k + 1][a_m] = ra.y;
                As[a_k + 2][a_m] = ra.z;
                As[a_k + 3][a_m] = ra.w;
                *(float4*)&Bs[b_k][b_n] = rb;
                __syncthreads();

                if (t + 1 < NT) {
                    int kk0 = k0 + (t + 1) * 16;
                    ra = *(const float4*)(A + (size_t)(m0 + a_m) * KBIG + kk0 + a_k);
                    int kg = kk0 + b_k;
                    int wr = c_WOFF[kg >> 9] + (kg & 511);
                    rb = *(const float4*)(Bm + (size_t)wr * 512 + n0 + b_n);
                }

                #pragma unroll
                for (int kk = 0; kk < 16; ++kk) {
                    float af[4], bf[4];
                    #pragma unroll
                    for (int i = 0; i < 4; ++i) af[i] = As[kk][ty * 4 + i];
                    #pragma unroll
                    for (int j = 0; j < 4; ++j) bf[j] = Bs[kk][tx * 4 + j];
                    #pragma unroll
                    for (int i = 0; i < 4; ++i)
                        #pragma unroll
                        for (int j = 0; j < 4; ++j)
                            acc[i][j] = fmaf(af[i], bf[j], acc[i][j]);
                }
                __syncthreads();
            }

            #pragma unroll
            for (int i = 0; i < 4; ++i) {
                int row = m0 + ty * 4 + i;
                #pragma unroll
                for (int j = 0; j < 4; ++j)
                    C[(size_t)row * 512 + n0 + tx * 4 + j] = acc[i][j];
            }
            __syncthreads();
        }
    }
}

// ---------------------------------------------------------------------------
// Scalar split-K tiled fp32 GEMM (layers 2-3), 256 threads. (R9-proven)
// ---------------------------------------------------------------------------
template<int BM, int BN, int TM, int TN>
__global__ void __launch_bounds__(256) gemm_split(
        const float* __restrict__ A, const float* __restrict__ Bm,
        int M, int N, int K, int Kc) {
    constexpr int BK = 16;
    constexpr int TX = BN / TN;
    constexpr int TY = BM / TM;
    static_assert(TX * TY == 256, "256 threads");
    static_assert(BN == 64, "B-tile loader assumes BN==64");

    __shared__ float As[BK][BM + 4];
    __shared__ float Bs[BK][BN + 4];

    const int tid = threadIdx.x;
    const int tx = tid % TX, ty = tid / TX;
    const int m0 = blockIdx.y * BM, n0 = blockIdx.x * BN;
    const int k0 = blockIdx.z * Kc;
    float* C = g_part + (size_t)blockIdx.z * M * N;

    const int  a_m   = tid >> 2;
    const int  a_k   = (tid & 3) << 2;
    const bool a_act = (BM * 4 >= 256) ? true : (tid < BM * 4);
    const int  b_k = tid >> 4;
    const int  b_n = (tid & 15) << 2;

    float4 ra = make_float4(0.f, 0.f, 0.f, 0.f);
    float4 rb;

    if (a_act) ra = *(const float4*)(A + (size_t)(m0 + a_m) * K + k0 + a_k);
    rb = *(const float4*)(Bm + (size_t)(k0 + b_k) * N + n0 + b_n);

    float acc[TM][TN];
    #pragma unroll
    for (int i = 0; i < TM; ++i)
        #pragma unroll
        for (int j = 0; j < TN; ++j) acc[i][j] = 0.f;

    const int NT = Kc / BK;
    for (int t = 0; t < NT; ++t) {
        if (a_act) {
            As[a_k + 0][a_m] = ra.x;
            As[a_k + 1][a_m] = ra.y;
            As[a_k + 2][a_m] = ra.z;
            As[a_k + 3][a_m] = ra.w;
        }
        *(float4*)&Bs[b_k][b_n] = rb;
        __syncthreads();

        if (t + 1 < NT) {
            int kk0 = k0 + (t + 1) * BK;
            if (a_act) ra = *(const float4*)(A + (size_t)(m0 + a_m) * K + kk0 + a_k);
            rb = *(const float4*)(Bm + (size_t)(kk0 + b_k) * N + n0 + b_n);
        }

        #pragma unroll
        for (int kk = 0; kk < BK; ++kk) {
            float af[TM], bf[TN];
            #pragma unroll
            for (int i = 0; i < TM; ++i) af[i] = As[kk][ty * TM + i];
            #pragma unroll
            for (int j = 0; j < TN; ++j) bf[j] = Bs[kk][tx * TN + j];
            #pragma unroll
            for (int i = 0; i < TM; ++i)
                #pragma unroll
                for (int j = 0; j < TN; ++j)
                    acc[i][j] = fmaf(af[i], bf[j], acc[i][j]);
        }
        __syncthreads();
    }

    #pragma unroll
    for (int i = 0; i < TM; ++i) {
        int row = m0 + ty * TM + i;
        #pragma unroll
        for (int j = 0; j < TN; ++j)
            C[(size_t)row * N + n0 + tx * TN + j] = acc[i][j];
    }
}

// ---------------------------------------------------------------------------
// out = act(sum_z part[z] + bias [+ C0]); fixed order -> deterministic.
// ---------------------------------------------------------------------------
template<int S, bool RELU, bool ADDC0>
__global__ void combine_k(const float* __restrict__ bias,
                          const float* __restrict__ C0,
                          float* __restrict__ out, int MN4, int N4) {
    int i = blockIdx.x * blockDim.x + threadIdx.x;
    if (i >= MN4) return;
    const float4* p = (const float4*)g_part;
    float4 v = __ldg(&((const float4*)bias)[i % N4]);
    #pragma unroll
    for (int s = 0; s < S; ++s) {
        float4 q = p[(size_t)s * MN4 + i];
        v.x += q.x; v.y += q.y; v.z += q.z; v.w += q.w;
    }
    if (ADDC0) {
        float4 c = ((const float4*)C0)[i];
        v.x += c.x; v.y += c.y; v.z += c.z; v.w += c.w;
    }
    if (RELU) {
        v.x = fmaxf(v.x, 0.f); v.y = fmaxf(v.y, 0.f);
        v.z = fmaxf(v.z, 0.f); v.w = fmaxf(v.w, 0.f);
    }
    ((float4*)out)[i] = v;
}

// ---------------------------------------------------------------------------
extern "C" void kernel_launch(void* const* d_in, const int* in_sizes, int n_in,
                              void* d_out, int out_size) {
    (void)in_sizes; (void)n_in; (void)out_size;

    const float* T_name        = (const float*)d_in[0];
    const float* T_collab      = (const float*)d_in[1];
    const float* T_track_can   = (const float*)d_in[2];
    const float* T_artist_name = (const float*)d_in[3];
    const float* T_track_uri   = (const float*)d_in[4];
    const float* T_track_name  = (const float*)d_in[5];
    const float* T_dur         = (const float*)d_in[6];
    const float* T_album       = (const float*)d_in[7];
    const float* T_apop        = (const float*)d_in[8];
    const float* T_afol        = (const float*)d_in[9];
    const float* T_tpop        = (const float*)d_in[10];
    const float* T_genres      = (const float*)d_in[11];
    const float* W1 = (const float*)d_in[12];
    const float* b1 = (const float*)d_in[13];
    const float* W2 = (const float*)d_in[14];
    const float* b2 = (const float*)d_in[15];
    const float* W3 = (const float*)d_in[16];
    const float* b3 = (const float*)d_in[17];
    const int* id_name         = (const int*)d_in[18];
    const int* id_collab       = (const int*)d_in[19];
    const int* id_track_can    = (const int*)d_in[20];
    const int* seq_artist_name = (const int*)d_in[21];
    const int* seq_track_uri   = (const int*)d_in[22];
    const int* seq_track_name  = (const int*)d_in[23];
    const int* seq_dur         = (const int*)d_in[24];
    const int* seq_album       = (const int*)d_in[25];
    const int* seq_apop        = (const int*)d_in[26];
    const int* seq_afol        = (const int*)d_in[27];
    const int* seq_tpop        = (const int*)d_in[28];
    const int* seq_genres      = (const int*)d_in[29];

    float *Y0, *H1, *H2;
    cudaGetSymbolAddress((void**)&Y0, g_Y0);
    cudaGetSymbolAddress((void**)&H1, g_H1);
    cudaGetSymbolAddress((void**)&H2, g_H2);

    MegaArgs ma;
    ma.tbl[0] = T_name;        ma.idx[0] = id_name;
    ma.tbl[1] = T_track_can;   ma.idx[1] = id_track_can;
    ma.tbl[2] = T_artist_name; ma.idx[2] = seq_artist_name;
    ma.tbl[3] = T_track_uri;   ma.idx[3] = seq_track_uri;
    ma.tbl[4] = T_track_name;  ma.idx[4] = seq_track_name;
    ma.tbl[5] = T_album;       ma.idx[5] = seq_album;
    ma.tbl[6] = T_genres;      ma.idx[6] = seq_genres;
    ma.W1 = W1;

    // independent small-feature fold (cheap, serial at front)
    precompute_P<<<88, 512>>>(T_collab, T_dur, T_apop, T_afol, T_tpop, W1);
    small_pool<<<NB, 128>>>(id_collab, seq_dur, seq_apop, seq_afol, seq_tpop);

    // fused pooling + GEMM1 (persistent, interleaved ticket queue)
    init_mega<<<1, 128>>>();
    mega<<<592, 256>>>(ma);

    // H1 = relu(sum_z part[z] + Y0 + b1)
    combine_k<7, true, true><<<(NB * 512 / 4 + 255) / 256, 256>>>(
        b1, Y0, H1, NB * 512 / 4, 512 / 4);

    // layer 2: [1024,512] @ W2; split-K=2 (Kc=256) -> 256 blocks
    gemm_split<32, 64, 2, 4><<<dim3(256 / 64, NB / 32, 2), 256>>>(
        H1, W2, NB, 256, 512, 256);
    combine_k<2, true, false><<<(NB * 256 / 4 + 255) / 256, 256>>>(
        b2, nullptr, H2, NB * 256 / 4, 256 / 4);

    // layer 3: [1024,256] @ W3; split-K=4 (Kc=64) -> 256 blocks
    gemm_split<32, 64, 2, 4><<<dim3(128 / 64, NB / 32, 4), 256>>>(
        H2, W3, NB, 128, 256, 64);
    combine_k<4, false, false><<<(NB * 128 / 4 + 255) / 256, 256>>>(
        b3, nullptr, (float*)d_out, NB * 128 / 4, 128 / 4);
}

// round 13
// speedup vs baseline: 1.1475x; 1.1219x over previous
#include <cuda_runtime.h>
#include <cstdint>

// ---------------------------------------------------------------------------
// Playlist model:
//   12 embedding towers (3 single-lookup, 9 mean-pooled over L=100)
//   -> concat [B, 12*512] -> Dense(512) relu -> Dense(256) relu -> Dense(128)
//
// R13 structure:
//   * Small tables folded through W1 by linearity -> Y0 [B,512] (g_P 88x512).
//   * FUSED persistent kernel (ticket queue) overlaps pooling with GEMM1.
//     R13 replaces the register-limited LDG pooling (measured ~6.5 B/cyc per
//     block) with cp.async.cg deep pipelines: each thread owns a private 16B
//     column slice, ring of 2 groups x 5 rows (20KB in flight per half-block,
//     no inner-loop barriers, no register pressure, no L1 pollution).
//     ~10x per-block gather rate -> few blocks saturate DRAM while the rest
//     run gemm tiles.
//   * Queue: 64 copies + 128 groups of [20 pool, 7 gemm]; pool f-major,
//     gemm z-major; gemm tiles gate on per-(feature, 64-row-block) counters.
//   * Deadlock-free: tiles wait only on strictly-earlier tickets; producers
//     never wait. Fixed-order math (deterministic).
// ---------------------------------------------------------------------------

#define NB   1024
#define NL   100
#define KBIG 3584          // 7 * 512

__device__ float g_X   [NB * KBIG];
__device__ float g_Y0  [NB * 512];
__device__ float g_P   [88 * 512];
__device__ float g_H1  [NB * 512];
__device__ float g_H2  [NB * 256];
__device__ float g_part[7 * NB * 512];     // split-K partials (7 x 1024 x 512)

__device__ int g_ticket;
__device__ int g_cnt[7][16];               // per (feature, 64-row block)

// W1 row offsets for the 7 big features in X-column order:
// name, track_can, artist_name, track_uri, track_name, album, genres
__constant__ int c_WOFF[7] = {0, 1024, 1536, 2048, 2560, 3584, 5632};

// Work queue: 64 copy items, then 128 groups of [20 pool, 7 gemm].
// pool stream: 5 features x 512 items (2 rows each), f-major, sub-major.
// gemm stream: 7 z x 128 tiles (64x64), z-major, mblk-major.
#define IT_COPY   64
#define N_ITEMS   (IT_COPY + 128 * 27)    // 3520

// ---------------------------------------------------------------------------
__device__ __forceinline__ unsigned smem_u32(const void* p) {
    return (unsigned)__cvta_generic_to_shared(p);
}
__device__ __forceinline__ void cp16(unsigned dst, const void* src) {
    asm volatile("cp.async.cg.shared.global [%0], [%1], 16;" :: "r"(dst), "l"(src));
}
__device__ __forceinline__ void cp_commit() {
    asm volatile("cp.async.commit_group;");
}
template<int N>
__device__ __forceinline__ void cp_wait() {
    asm volatile("cp.async.wait_group %0;" :: "n"(N));
}

// ---------------------------------------------------------------------------
__global__ void init_mega() {
    if (threadIdx.x == 0) g_ticket = 0;
    if (threadIdx.x < 112) ((int*)g_cnt)[threadIdx.x] = 0;
}

// ---------------------------------------------------------------------------
__global__ void precompute_P(const float* __restrict__ T_collab,
                             const float* __restrict__ T_dur,
                             const float* __restrict__ T_apop,
                             const float* __restrict__ T_afol,
                             const float* __restrict__ T_tpop,
                             const float* __restrict__ W1) {
    __shared__ float s_t[512];
    int r = blockIdx.x;
    const float* T; int row; int off;
    if (r < 4)       { T = T_collab; row = r;      off = 512;  }
    else if (r < 25) { T = T_dur;    row = r - 4;  off = 3072; }
    else if (r < 46) { T = T_apop;   row = r - 25; off = 4096; }
    else if (r < 67) { T = T_afol;   row = r - 46; off = 4608; }
    else             { T = T_tpop;   row = r - 67; off = 5120; }
    int n = threadIdx.x;                       // 512 threads
    s_t[n] = T[row * 512 + n];
    __syncthreads();
    float acc = 0.0f;
    const float* w = W1 + (size_t)off * 512 + n;
    #pragma unroll 8
    for (int k = 0; k < 512; ++k)
        acc = fmaf(s_t[k], w[(size_t)k * 512], acc);
    g_P[r * 512 + n] = acc;
}

// ---------------------------------------------------------------------------
__global__ void small_pool(const int* __restrict__ id_collab,
                           const int* __restrict__ seq_dur,
                           const int* __restrict__ seq_apop,
                           const int* __restrict__ seq_afol,
                           const int* __restrict__ seq_tpop) {
    __shared__ int cnt[21];
    const int b = blockIdx.x, t = threadIdx.x;     // 128 threads, float4 lanes
    const float4* P4 = (const float4*)g_P;

    const int idc = id_collab[b];
    float4 acc = __ldg(&P4[(size_t)idc * 128 + t]);
    float4 ab  = make_float4(0.f, 0.f, 0.f, 0.f);

    const int* seqs[4]  = {seq_dur, seq_apop, seq_afol, seq_tpop};
    const int  pbase[4] = {4, 25, 46, 67};

    for (int j = 0; j < 4; ++j) {
        if (t < 21) cnt[t] = 0;
        __syncthreads();
        if (t < NL) atomicAdd(&cnt[seqs[j][b * NL + t]], 1);
        __syncthreads();
        #pragma unroll
        for (int v = 0; v < 21; ++v) {
            int c = cnt[v];
            if (c) {
                float fc = (float)c;
                float4 p = __ldg(&P4[(size_t)(pbase[j] + v) * 128 + t]);
                ab.x = fmaf(fc, p.x, ab.x);
                ab.y = fmaf(fc, p.y, ab.y);
                ab.z = fmaf(fc, p.z, ab.z);
                ab.w = fmaf(fc, p.w, ab.w);
            }
        }
        __syncthreads();
    }
    float4 o;
    o.x = acc.x + 0.01f * ab.x;
    o.y = acc.y + 0.01f * ab.y;
    o.z = acc.z + 0.01f * ab.z;
    o.w = acc.w + 0.01f * ab.w;
    ((float4*)g_Y0)[(size_t)b * 128 + t] = o;
}

// ---------------------------------------------------------------------------
// Fused persistent pooling + GEMM1 kernel.
// smem layout (floats):
//   [0 .. 10240)      pool rings: half h at h*5120 (2 groups x 5 rows x 512)
//                     gemm overlays [0 .. 2176) (As 16x68 + Bs 16x68)
//   [10240 .. 10496)  staged indices: half h at 10240 + h*128 (ints)
// ---------------------------------------------------------------------------
struct MegaArgs {
    const float* tbl[7];    // tables in X feature order
    const int*   idx[7];    // f<2: [B] ids; f>=2: [B,L] sequences
    const float* W1;
};

__global__ void __launch_bounds__(256) mega(MegaArgs a) {
    __shared__ __align__(16) float smem[10496];
    __shared__ int s_item;

    const int tid = threadIdx.x;
    float4* X4 = (float4*)g_X;

    for (;;) {
        if (tid == 0) s_item = atomicAdd(&g_ticket, 1);
        __syncthreads();
        const int it = s_item;
        if (it >= N_ITEMS) break;   // uniform exit

        // ---- decode: 64 copies, then groups of [20 pool, 7 gemm] ----
        int kind;      // 0=copy, 1=pool, 2=gemm
        int f = 0, sub = 0, z = 0, r = 0;
        if (it < IT_COPY) { kind = 0; sub = it; }
        else {
            int t2 = it - IT_COPY;
            int g = t2 / 27, l = t2 - g * 27;
            if (l < 20) { int p = g * 20 + l;        kind = 1; f = 2 + (p >> 9); sub = p & 511; }
            else        { int q = g * 7 + (l - 20);  kind = 2; z = q >> 7;       r = q & 127; }
        }

        if (kind == 0) {
            // ---- copy item: 16 b's x 2 single-lookup features ----
            const int b0 = sub * 16;
            const int feat = tid >> 7;           // 0 or 1
            const int col  = tid & 127;
            const float4* T = (const float4*)a.tbl[feat];
            #pragma unroll 4
            for (int k = 0; k < 16; ++k) {
                int b  = b0 + k;
                int id = a.idx[feat][b];
                X4[(size_t)b * 896 + feat * 128 + col] =
                    __ldg(&T[(size_t)id * 128 + col]);
            }
            __threadfence();
            __syncthreads();
            if (tid == 0) {
                atomicAdd(&g_cnt[0][sub >> 2], 1);
                atomicAdd(&g_cnt[1][sub >> 2], 1);
            }
        } else if (kind == 1) {
            // ---- pool item: 2 rows of feature f via cp.async pipelines ----
            const int b0 = sub * 2;
            int* sidx = (int*)(smem + 10240);
            const int* seq = a.idx[f] + b0 * NL;
            for (int i = tid; i < 2 * NL; i += 256)
                sidx[(i / NL) * 128 + (i % NL)] = seq[i];
            __syncthreads();

            const int h = tid >> 7, lt = tid & 127;
            const int* sx = sidx + h * 128;            // 100 indices (bcast LDS)
            const float* Tb = a.tbl[f] + lt * 4;       // this thread's column
            float* ring = smem + h * 5120;             // 2 x 5 x 512 floats
            const unsigned rb = smem_u32(ring) + lt * 16;

            // prologue: issue groups 0 and 1 (5 rows each)
            #pragma unroll
            for (int g0 = 0; g0 < 2; ++g0) {
                #pragma unroll
                for (int q = 0; q < 5; ++q)
                    cp16(rb + (unsigned)(g0 * 5 + q) * 2048,
                         Tb + (size_t)sx[g0 * 5 + q] * 512);
                cp_commit();
            }

            float4 acc = make_float4(0.f, 0.f, 0.f, 0.f);
            for (int g = 0; g < 20; ++g) {
                if (g == 19) cp_wait<0>(); else cp_wait<1>();
                const int buf = g & 1;
                // consume 5 rows (this thread's own 16B slices)
                #pragma unroll
                for (int q = 0; q < 5; ++q) {
                    float4 v = *(const float4*)(ring + (buf * 5 + q) * 512 + lt * 4);
                    acc.x += v.x; acc.y += v.y; acc.z += v.z; acc.w += v.w;
                }
                // refill freed buffer with group g+2 (writes land ~600cyc later,
                // well after the in-order LDS reads above executed)
                if (g + 2 < 20) {
                    #pragma unroll
                    for (int q = 0; q < 5; ++q)
                        cp16(rb + (unsigned)(buf * 5 + q) * 2048,
                             Tb + (size_t)sx[(g + 2) * 5 + q] * 512);
                    cp_commit();
                }
            }
            acc.x *= 0.01f; acc.y *= 0.01f; acc.z *= 0.01f; acc.w *= 0.01f;
            X4[(size_t)(b0 + h) * 896 + f * 128 + lt] = acc;

            __threadfence();
            __syncthreads();
            if (tid == 0) atomicAdd(&g_cnt[f][sub >> 5], 1);
        } else {
            // ---- gemm tile: 64x64, Kc=512 (feature z), split-K partial ----
            const int mblk = r >> 3, nblk = r & 7;
            const int tgt = (z < 2) ? 4 : 32;
            if (tid == 0) {
                while (atomicAdd(&g_cnt[z][mblk], 0) < tgt) __nanosleep(200);
                __threadfence();
            }
            __syncthreads();

            float (*As)[68] = (float(*)[68])smem;
            float (*Bs)[68] = (float(*)[68])(smem + 16 * 68);

            const int tx = tid & 15, ty = tid >> 4;
            const int m0 = mblk * 64, n0 = nblk * 64;
            const int k0 = z * 512;
            float* C = g_part + (size_t)z * NB * 512;

            const int a_m = tid >> 2;
            const int a_k = (tid & 3) << 2;
            const int b_k = tid >> 4;
            const int b_n = (tid & 15) << 2;

            const float* A = g_X;
            const float* Bm = a.W1;

            float4 ra = *(const float4*)(A + (size_t)(m0 + a_m) * KBIG + k0 + a_k);
            float4 rbv;
            {
                int kg = k0 + b_k;
                int wr = c_WOFF[kg >> 9] + (kg & 511);
                rbv = *(const float4*)(Bm + (size_t)wr * 512 + n0 + b_n);
            }

            float acc[4][4];
            #pragma unroll
            for (int i = 0; i < 4; ++i)
                #pragma unroll
                for (int j = 0; j < 4; ++j) acc[i][j] = 0.f;

            const int NT = 512 / 16;
            for (int t = 0; t < NT; ++t) {
                As[a_k + 0][a_m] = ra.x;
                As[a_k + 1][a_m] = ra.y;
                As[a_k + 2][a_m] = ra.z;
                As[a_k + 3][a_m] = ra.w;
                *(float4*)&Bs[b_k][b_n] = rbv;
                __syncthreads();

                if (t + 1 < NT) {
                    int kk0 = k0 + (t + 1) * 16;
                    ra = *(const float4*)(A + (size_t)(m0 + a_m) * KBIG + kk0 + a_k);
                    int kg = kk0 + b_k;
                    int wr = c_WOFF[kg >> 9] + (kg & 511);
                    rbv = *(const float4*)(Bm + (size_t)wr * 512 + n0 + b_n);
                }

                #pragma unroll
                for (int kk = 0; kk < 16; ++kk) {
                    float af[4], bf[4];
                    #pragma unroll
                    for (int i = 0; i < 4; ++i) af[i] = As[kk][ty * 4 + i];
                    #pragma unroll
                    for (int j = 0; j < 4; ++j) bf[j] = Bs[kk][tx * 4 + j];
                    #pragma unroll
                    for (int i = 0; i < 4; ++i)
                        #pragma unroll
                        for (int j = 0; j < 4; ++j)
                            acc[i][j] = fmaf(af[i], bf[j], acc[i][j]);
                }
                __syncthreads();
            }

            #pragma unroll
            for (int i = 0; i < 4; ++i) {
                int row = m0 + ty * 4 + i;
                #pragma unroll
                for (int j = 0; j < 4; ++j)
                    C[(size_t)row * 512 + n0 + tx * 4 + j] = acc[i][j];
            }
            __syncthreads();
        }
    }
}

// ---------------------------------------------------------------------------
// Scalar split-K tiled fp32 GEMM (layers 2-3), 256 threads. (R9-proven)
// ---------------------------------------------------------------------------
template<int BM, int BN, int TM, int TN>
__global__ void __launch_bounds__(256) gemm_split(
        const float* __restrict__ A, const float* __restrict__ Bm,
        int M, int N, int K, int Kc) {
    constexpr int BK = 16;
    constexpr int TX = BN / TN;
    constexpr int TY = BM / TM;
    static_assert(TX * TY == 256, "256 threads");
    static_assert(BN == 64, "B-tile loader assumes BN==64");

    __shared__ float As[BK][BM + 4];
    __shared__ float Bs[BK][BN + 4];

    const int tid = threadIdx.x;
    const int tx = tid % TX, ty = tid / TX;
    const int m0 = blockIdx.y * BM, n0 = blockIdx.x * BN;
    const int k0 = blockIdx.z * Kc;
    float* C = g_part + (size_t)blockIdx.z * M * N;

    const int  a_m   = tid >> 2;
    const int  a_k   = (tid & 3) << 2;
    const bool a_act = (BM * 4 >= 256) ? true : (tid < BM * 4);
    const int  b_k = tid >> 4;
    const int  b_n = (tid & 15) << 2;

    float4 ra = make_float4(0.f, 0.f, 0.f, 0.f);
    float4 rb;

    if (a_act) ra = *(const float4*)(A + (size_t)(m0 + a_m) * K + k0 + a_k);
    rb = *(const float4*)(Bm + (size_t)(k0 + b_k) * N + n0 + b_n);

    float acc[TM][TN];
    #pragma unroll
    for (int i = 0; i < TM; ++i)
        #pragma unroll
        for (int j = 0; j < TN; ++j) acc[i][j] = 0.f;

    const int NT = Kc / BK;
    for (int t = 0; t < NT; ++t) {
        if (a_act) {
            As[a_k + 0][a_m] = ra.x;
            As[a_k + 1][a_m] = ra.y;
            As[a_k + 2][a_m] = ra.z;
            As[a_k + 3][a_m] = ra.w;
        }
        *(float4*)&Bs[b_k][b_n] = rb;
        __syncthreads();

        if (t + 1 < NT) {
            int kk0 = k0 + (t + 1) * BK;
            if (a_act) ra = *(const float4*)(A + (size_t)(m0 + a_m) * K + kk0 + a_k);
            rb = *(const float4*)(Bm + (size_t)(kk0 + b_k) * N + n0 + b_n);
        }

        #pragma unroll
        for (int kk = 0; kk < BK; ++kk) {
            float af[TM], bf[TN];
            #pragma unroll
            for (int i = 0; i < TM; ++i) af[i] = As[kk][ty * TM + i];
            #pragma unroll
            for (int j = 0; j < TN; ++j) bf[j] = Bs[kk][tx * TN + j];
            #pragma unroll
            for (int i = 0; i < TM; ++i)
                #pragma unroll
                for (int j = 0; j < TN; ++j)
                    acc[i][j] = fmaf(af[i], bf[j], acc[i][j]);
        }
        __syncthreads();
    }

    #pragma unroll
    for (int i = 0; i < TM; ++i) {
        int row = m0 + ty * TM + i;
        #pragma unroll
        for (int j = 0; j < TN; ++j)
            C[(size_t)row * N + n0 + tx * TN + j] = acc[i][j];
    }
}

// ---------------------------------------------------------------------------
// out = act(sum_z part[z] + bias [+ C0]); fixed order -> deterministic.
// ---------------------------------------------------------------------------
template<int S, bool RELU, bool ADDC0>
__global__ void combine_k(const float* __restrict__ bias,
                          const float* __restrict__ C0,
                          float* __restrict__ out, int MN4, int N4) {
    int i = blockIdx.x * blockDim.x + threadIdx.x;
    if (i >= MN4) return;
    const float4* p = (const float4*)g_part;
    float4 v = __ldg(&((const float4*)bias)[i % N4]);
    #pragma unroll
    for (int s = 0; s < S; ++s) {
        float4 q = p[(size_t)s * MN4 + i];
        v.x += q.x; v.y += q.y; v.z += q.z; v.w += q.w;
    }
    if (ADDC0) {
        float4 c = ((const float4*)C0)[i];
        v.x += c.x; v.y += c.y; v.z += c.z; v.w += c.w;
    }
    if (RELU) {
        v.x = fmaxf(v.x, 0.f); v.y = fmaxf(v.y, 0.f);
        v.z = fmaxf(v.z, 0.f); v.w = fmaxf(v.w, 0.f);
    }
    ((float4*)out)[i] = v;
}

// ---------------------------------------------------------------------------
extern "C" void kernel_launch(void* const* d_in, const int* in_sizes, int n_in,
                              void* d_out, int out_size) {
    (void)in_sizes; (void)n_in; (void)out_size;

    const float* T_name        = (const float*)d_in[0];
    const float* T_collab      = (const float*)d_in[1];
    const float* T_track_can   = (const float*)d_in[2];
    const float* T_artist_name = (const float*)d_in[3];
    const float* T_track_uri   = (const float*)d_in[4];
    const float* T_track_name  = (const float*)d_in[5];
    const float* T_dur         = (const float*)d_in[6];
    const float* T_album       = (const float*)d_in[7];
    const float* T_apop        = (const float*)d_in[8];
    const float* T_afol        = (const float*)d_in[9];
    const float* T_tpop        = (const float*)d_in[10];
    const float* T_genres      = (const float*)d_in[11];
    const float* W1 = (const float*)d_in[12];
    const float* b1 = (const float*)d_in[13];
    const float* W2 = (const float*)d_in[14];
    const float* b2 = (const float*)d_in[15];
    const float* W3 = (const float*)d_in[16];
    const float* b3 = (const float*)d_in[17];
    const int* id_name         = (const int*)d_in[18];
    const int* id_collab       = (const int*)d_in[19];
    const int* id_track_can    = (const int*)d_in[20];
    const int* seq_artist_name = (const int*)d_in[21];
    const int* seq_track_uri   = (const int*)d_in[22];
    const int* seq_track_name  = (const int*)d_in[23];
    const int* seq_dur         = (const int*)d_in[24];
    const int* seq_album       = (const int*)d_in[25];
    const int* seq_apop        = (const int*)d_in[26];
    const int* seq_afol        = (const int*)d_in[27];
    const int* seq_tpop        = (const int*)d_in[28];
    const int* seq_genres      = (const int*)d_in[29];

    float *Y0, *H1, *H2;
    cudaGetSymbolAddress((void**)&Y0, g_Y0);
    cudaGetSymbolAddress((void**)&H1, g_H1);
    cudaGetSymbolAddress((void**)&H2, g_H2);

    MegaArgs ma;
    ma.tbl[0] = T_name;        ma.idx[0] = id_name;
    ma.tbl[1] = T_track_can;   ma.idx[1] = id_track_can;
    ma.tbl[2] = T_artist_name; ma.idx[2] = seq_artist_name;
    ma.tbl[3] = T_track_uri;   ma.idx[3] = seq_track_uri;
    ma.tbl[4] = T_track_name;  ma.idx[4] = seq_track_name;
    ma.tbl[5] = T_album;       ma.idx[5] = seq_album;
    ma.tbl[6] = T_genres;      ma.idx[6] = seq_genres;
    ma.W1 = W1;

    // independent small-feature fold (cheap, serial at front)
    precompute_P<<<88, 512>>>(T_collab, T_dur, T_apop, T_afol, T_tpop, W1);
    small_pool<<<NB, 128>>>(id_collab, seq_dur, seq_apop, seq_afol, seq_tpop);

    // fused pooling + GEMM1 (persistent, interleaved ticket queue)
    init_mega<<<1, 128>>>();
    mega<<<592, 256>>>(ma);

    // H1 = relu(sum_z part[z] + Y0 + b1)
    combine_k<7, true, true><<<(NB * 512 / 4 + 255) / 256, 256>>>(
        b1, Y0, H1, NB * 512 / 4, 512 / 4);

    // layer 2: [1024,512] @ W2; split-K=2 (Kc=256) -> 256 blocks
    gemm_split<32, 64, 2, 4><<<dim3(256 / 64, NB / 32, 2), 256>>>(
        H1, W2, NB, 256, 512, 256);
    combine_k<2, true, false><<<(NB * 256 / 4 + 255) / 256, 256>>>(
        b2, nullptr, H2, NB * 256 / 4, 256 / 4);

    // layer 3: [1024,256] @ W3; split-K=4 (Kc=64) -> 256 blocks
    gemm_split<32, 64, 2, 4><<<dim3(128 / 64, NB / 32, 4), 256>>>(
        H2, W3, NB, 128, 256, 64);
    combine_k<4, false, false><<<(NB * 128 / 4 + 255) / 256, 256>>>(
        b3, nullptr, (float*)d_out, NB * 128 / 4, 128 / 4);
}

// round 14
// speedup vs baseline: 1.1847x; 1.0324x over previous
#include <cuda_runtime.h>
#include <cstdint>

// ---------------------------------------------------------------------------
// Playlist model:
//   12 embedding towers (3 single-lookup, 9 mean-pooled over L=100)
//   -> concat [B, 12*512] -> Dense(512) relu -> Dense(256) relu -> Dense(128)
//
// R14 structure:
//   * Small tables folded through W1 by linearity -> Y0 [B,512] (g_P 88x512).
//   * FUSED persistent kernel (ticket queue) overlaps pooling with GEMM1.
//     R14 moves the row gathers from cp.async (which still consumes L1tex
//     wavefronts -- measured co-saturation with the GEMM's LDS at ~68%) to
//     TMA bulk copies (cp.async.bulk, a DMA path with zero L1 involvement
//     and one issuing thread per 2KB row). Per half-block: 2-slot mbarrier
//     ring of 5-row (10KB) groups; consumers try_wait.acquire, read float4
//     slices, named-bar.sync, producer refills. mbarriers init once per
//     block; phase cursors in registers across ticket items.
//   * Queue: 64 copies + 128 groups of [20 pool, 7 gemm]; pool f-major,
//     gemm z-major; gemm tiles gate on per-(feature, 64-row-block) counters.
//   * Deadlock-free: tiles wait only on strictly-earlier tickets; producers
//     never wait. Fixed-order math (deterministic).
// ---------------------------------------------------------------------------

#define NB   1024
#define NL   100
#define KBIG 3584          // 7 * 512

__device__ float g_X   [NB * KBIG];
__device__ float g_Y0  [NB * 512];
__device__ float g_P   [88 * 512];
__device__ float g_H1  [NB * 512];
__device__ float g_H2  [NB * 256];
__device__ float g_part[7 * NB * 512];     // split-K partials (7 x 1024 x 512)

__device__ int g_ticket;
__device__ int g_cnt[7][16];               // per (feature, 64-row block)

// W1 row offsets for the 7 big features in X-column order:
// name, track_can, artist_name, track_uri, track_name, album, genres
__constant__ int c_WOFF[7] = {0, 1024, 1536, 2048, 2560, 3584, 5632};

// Work queue: 64 copy items, then 128 groups of [20 pool, 7 gemm].
#define IT_COPY   64
#define N_ITEMS   (IT_COPY + 128 * 27)    // 3520

// ---------------------------------------------------------------------------
__device__ __forceinline__ unsigned smem_u32(const void* p) {
    return (unsigned)__cvta_generic_to_shared(p);
}
__device__ __forceinline__ void mbar_init(unsigned mbar, unsigned cnt) {
    asm volatile("mbarrier.init.shared.b64 [%0], %1;" :: "r"(mbar), "r"(cnt) : "memory");
}
__device__ __forceinline__ void mbar_expect_tx(unsigned mbar, unsigned bytes) {
    asm volatile("mbarrier.arrive.expect_tx.shared.b64 _, [%0], %1;"
                 :: "r"(mbar), "r"(bytes) : "memory");
}
__device__ __forceinline__ void mbar_wait(unsigned mbar, int phase) {
    asm volatile(
        "{\n\t.reg .pred P;\n"
        "W%=:\n\t"
        "mbarrier.try_wait.parity.acquire.cta.shared::cta.b64 P, [%0], %1, 0x989680;\n\t"
        "@!P bra W%=;\n\t}"
        :: "r"(mbar), "r"(phase) : "memory");
}
__device__ __forceinline__ void tma_row(unsigned dst, const void* src) {
    // 2KB global->shared bulk copy, completion via mbarrier tx accounting.
    // NOTE: mbar operand is the LAST operand per PTX ISA.
    asm volatile(
        "cp.async.bulk.shared::cluster.global.mbarrier::complete_tx::bytes "
        "[%0], [%1], %2, [%3];"
        :: "r"(dst), "l"(src), "r"(2048), "r"(dst + 0u /*dummy keep*/), "r"(0u) : "memory");
}

// ---------------------------------------------------------------------------
__global__ void init_mega() {
    if (threadIdx.x == 0) g_ticket = 0;
    if (threadIdx.x < 112) ((int*)g_cnt)[threadIdx.x] = 0;
}

// ---------------------------------------------------------------------------
__global__ void precompute_P(const float* __restrict__ T_collab,
                             const float* __restrict__ T_dur,
                             const float* __restrict__ T_apop,
                             const float* __restrict__ T_afol,
                             const float* __restrict__ T_tpop,
                             const float* __restrict__ W1) {
    __shared__ float s_t[512];
    int r = blockIdx.x;
    const float* T; int row; int off;
    if (r < 4)       { T = T_collab; row = r;      off = 512;  }
    else if (r < 25) { T = T_dur;    row = r - 4;  off = 3072; }
    else if (r < 46) { T = T_apop;   row = r - 25; off = 4096; }
    else if (r < 67) { T = T_afol;   row = r - 46; off = 4608; }
    else             { T = T_tpop;   row = r - 67; off = 5120; }
    int n = threadIdx.x;                       // 512 threads
    s_t[n] = T[row * 512 + n];
    __syncthreads();
    float acc = 0.0f;
    const float* w = W1 + (size_t)off * 512 + n;
    #pragma unroll 8
    for (int k = 0; k < 512; ++k)
        acc = fmaf(s_t[k], w[(size_t)k * 512], acc);
    g_P[r * 512 + n] = acc;
}

// ---------------------------------------------------------------------------
__global__ void small_pool(const int* __restrict__ id_collab,
                           const int* __restrict__ seq_dur,
                           const int* __restrict__ seq_apop,
                           const int* __restrict__ seq_afol,
                           const int* __restrict__ seq_tpop) {
    __shared__ int cnt[21];
    const int b = blockIdx.x, t = threadIdx.x;     // 128 threads, float4 lanes
    const float4* P4 = (const float4*)g_P;

    const int idc = id_collab[b];
    float4 acc = __ldg(&P4[(size_t)idc * 128 + t]);
    float4 ab  = make_float4(0.f, 0.f, 0.f, 0.f);

    const int* seqs[4]  = {seq_dur, seq_apop, seq_afol, seq_tpop};
    const int  pbase[4] = {4, 25, 46, 67};

    for (int j = 0; j < 4; ++j) {
        if (t < 21) cnt[t] = 0;
        __syncthreads();
        if (t < NL) atomicAdd(&cnt[seqs[j][b * NL + t]], 1);
        __syncthreads();
        #pragma unroll
        for (int v = 0; v < 21; ++v) {
            int c = cnt[v];
            if (c) {
                float fc = (float)c;
                float4 p = __ldg(&P4[(size_t)(pbase[j] + v) * 128 + t]);
                ab.x = fmaf(fc, p.x, ab.x);
                ab.y = fmaf(fc, p.y, ab.y);
                ab.z = fmaf(fc, p.z, ab.z);
                ab.w = fmaf(fc, p.w, ab.w);
            }
        }
        __syncthreads();
    }
    float4 o;
    o.x = acc.x + 0.01f * ab.x;
    o.y = acc.y + 0.01f * ab.y;
    o.z = acc.z + 0.01f * ab.z;
    o.w = acc.w + 0.01f * ab.w;
    ((float4*)g_Y0)[(size_t)b * 128 + t] = o;
}

// ---------------------------------------------------------------------------
// Fused persistent pooling + GEMM1 kernel.
// smem layout (floats):
//   [0 .. 10240)      pool rings: half h at h*5120 (2 slots x 5 rows x 512)
//                     gemm overlays [0 .. 2176) (As 16x68 + Bs 16x68)
//   [10240 .. 10496)  staged indices: half h at 10240 + h*128 (ints)
//   [10496 .. 10504)  4 mbarriers (u64): index h*2+s
// ---------------------------------------------------------------------------
struct MegaArgs {
    const float* tbl[7];    // tables in X feature order
    const int*   idx[7];    // f<2: [B] ids; f>=2: [B,L] sequences
    const float* W1;
};

__global__ void __launch_bounds__(256) mega(MegaArgs a) {
    __shared__ __align__(1024) float smem[10504];
    __shared__ int s_item;

    const int tid = threadIdx.x;
    float4* X4 = (float4*)g_X;

    // one-time mbarrier init (count=1: the producer's arrive.expect_tx)
    const unsigned mb_base = smem_u32(smem + 10496);
    if (tid == 0) {
        #pragma unroll
        for (int k = 0; k < 4; ++k) mbar_init(mb_base + 8 * k, 1);
    }
    __syncthreads();

    // per-thread phase cursors for this half's 2 ring slots
    int ph0 = 0, ph1 = 0;

    for (;;) {
        if (tid == 0) s_item = atomicAdd(&g_ticket, 1);
        __syncthreads();
        const int it = s_item;
        if (it >= N_ITEMS) break;   // uniform exit

        // ---- decode: 64 copies, then groups of [20 pool, 7 gemm] ----
        int kind;      // 0=copy, 1=pool, 2=gemm
        int f = 0, sub = 0, z = 0, r = 0;
        if (it < IT_COPY) { kind = 0; sub = it; }
        else {
            int t2 = it - IT_COPY;
            int g = t2 / 27, l = t2 - g * 27;
            if (l < 20) { int p = g * 20 + l;        kind = 1; f = 2 + (p >> 9); sub = p & 511; }
            else        { int q = g * 7 + (l - 20);  kind = 2; z = q >> 7;       r = q & 127; }
        }

        if (kind == 0) {
            // ---- copy item: 16 b's x 2 single-lookup features ----
            const int b0 = sub * 16;
            const int feat = tid >> 7;           // 0 or 1
            const int col  = tid & 127;
            const float4* T = (const float4*)a.tbl[feat];
            #pragma unroll 4
            for (int k = 0; k < 16; ++k) {
                int b  = b0 + k;
                int id = a.idx[feat][b];
                X4[(size_t)b * 896 + feat * 128 + col] =
                    __ldg(&T[(size_t)id * 128 + col]);
            }
            __threadfence();
            __syncthreads();
            if (tid == 0) {
                atomicAdd(&g_cnt[0][sub >> 2], 1);
                atomicAdd(&g_cnt[1][sub >> 2], 1);
            }
        } else if (kind == 1) {
            // ---- pool item: 2 rows of feature f via TMA bulk ring ----
            const int b0 = sub * 2;
            int* sidx = (int*)(smem + 10240);
            const int* seq = a.idx[f] + b0 * NL;
            for (int i = tid; i < 2 * NL; i += 256)
                sidx[(i / NL) * 128 + (i % NL)] = seq[i];
            __syncthreads();

            const int h = tid >> 7, lt = tid & 127;
            const int* sx = sidx + h * 128;          // 100 indices (bcast LDS)
            const float* Tb = a.tbl[f];
            float* ring = smem + h * 5120;           // 2 slots x 5 rows x 512
            const unsigned ring_u = smem_u32(ring);
            const unsigned mb0 = mb_base + 8 * (h * 2);
            const unsigned mb1 = mb_base + 8 * (h * 2 + 1);
            const bool prod = (lt == 0);

            // prologue: issue groups 0 (slot0) and 1 (slot1)
            if (prod) {
                mbar_expect_tx(mb0, 10240);
                #pragma unroll
                for (int q = 0; q < 5; ++q)
                    asm volatile(
                        "cp.async.bulk.shared::cluster.global.mbarrier::complete_tx::bytes "
                        "[%0], [%1], %2, [%3];"
                        :: "r"(ring_u + q * 2048u),
                           "l"(Tb + (size_t)sx[q] * 512), "r"(2048), "r"(mb0)
                        : "memory");
                mbar_expect_tx(mb1, 10240);
                #pragma unroll
                for (int q = 0; q < 5; ++q)
                    asm volatile(
                        "cp.async.bulk.shared::cluster.global.mbarrier::complete_tx::bytes "
                        "[%0], [%1], %2, [%3];"
                        :: "r"(ring_u + 10240u + q * 2048u),
                           "l"(Tb + (size_t)sx[5 + q] * 512), "r"(2048), "r"(mb1)
                        : "memory");
            }

            float4 acc = make_float4(0.f, 0.f, 0.f, 0.f);
            for (int g = 0; g < 20; ++g) {
                const int s = g & 1;
                if (s == 0) { mbar_wait(mb0, ph0); ph0 ^= 1; }
                else        { mbar_wait(mb1, ph1); ph1 ^= 1; }
                // consume 5 rows (this thread's own 16B slices)
                const float* buf = ring + s * 2560;
                #pragma unroll
                for (int q = 0; q < 5; ++q) {
                    float4 v = *(const float4*)(buf + q * 512 + lt * 4);
                    acc.x += v.x; acc.y += v.y; acc.z += v.z; acc.w += v.w;
                }
                // half-scope barrier: all reads done before producer reuses slot
                asm volatile("bar.sync %0, %1;" :: "r"(1 + h), "r"(128) : "memory");
                if (prod && g + 2 < 20) {
                    const unsigned mb = (s == 0) ? mb0 : mb1;
                    mbar_expect_tx(mb, 10240);
                    #pragma unroll
                    for (int q = 0; q < 5; ++q)
                        asm volatile(
                            "cp.async.bulk.shared::cluster.global.mbarrier::complete_tx::bytes "
                            "[%0], [%1], %2, [%3];"
                            :: "r"(ring_u + (unsigned)s * 10240u + q * 2048u),
                               "l"(Tb + (size_t)sx[(g + 2) * 5 + q] * 512),
                               "r"(2048), "r"(mb)
                            : "memory");
                }
            }
            acc.x *= 0.01f; acc.y *= 0.01f; acc.z *= 0.01f; acc.w *= 0.01f;
            X4[(size_t)(b0 + h) * 896 + f * 128 + lt] = acc;

            __threadfence();
            __syncthreads();
            if (tid == 0) atomicAdd(&g_cnt[f][sub >> 5], 1);
        } else {
            // ---- gemm tile: 64x64, Kc=512 (feature z), split-K partial ----
            const int mblk = r >> 3, nblk = r & 7;
            const int tgt = (z < 2) ? 4 : 32;
            if (tid == 0) {
                while (atomicAdd(&g_cnt[z][mblk], 0) < tgt) __nanosleep(200);
                __threadfence();
            }
            __syncthreads();

            float (*As)[68] = (float(*)[68])smem;
            float (*Bs)[68] = (float(*)[68])(smem + 16 * 68);

            const int tx = tid & 15, ty = tid >> 4;
            const int m0 = mblk * 64, n0 = nblk * 64;
            const int k0 = z * 512;
            float* C = g_part + (size_t)z * NB * 512;

            const int a_m = tid >> 2;
            const int a_k = (tid & 3) << 2;
            const int b_k = tid >> 4;
            const int b_n = (tid & 15) << 2;

            const float* A = g_X;
            const float* Bm = a.W1;

            float4 ra = *(const float4*)(A + (size_t)(m0 + a_m) * KBIG + k0 + a_k);
            float4 rbv;
            {
                int kg = k0 + b_k;
                int wr = c_WOFF[kg >> 9] + (kg & 511);
                rbv = *(const float4*)(Bm + (size_t)wr * 512 + n0 + b_n);
            }

            float acc[4][4];
            #pragma unroll
            for (int i = 0; i < 4; ++i)
                #pragma unroll
                for (int j = 0; j < 4; ++j) acc[i][j] = 0.f;

            const int NT = 512 / 16;
            for (int t = 0; t < NT; ++t) {
                As[a_k + 0][a_m] = ra.x;
                As[a_k + 1][a_m] = ra.y;
                As[a_k + 2][a_m] = ra.z;
                As[a_k + 3][a_m] = ra.w;
                *(float4*)&Bs[b_k][b_n] = rbv;
                __syncthreads();

                if (t + 1 < NT) {
                    int kk0 = k0 + (t + 1) * 16;
                    ra = *(const float4*)(A + (size_t)(m0 + a_m) * KBIG + kk0 + a_k);
                    int kg = kk0 + b_k;
                    int wr = c_WOFF[kg >> 9] + (kg & 511);
                    rbv = *(const float4*)(Bm + (size_t)wr * 512 + n0 + b_n);
                }

                #pragma unroll
                for (int kk = 0; kk < 16; ++kk) {
                    float af[4], bf[4];
                    #pragma unroll
                    for (int i = 0; i < 4; ++i) af[i] = As[kk][ty * 4 + i];
                    #pragma unroll
                    for (int j = 0; j < 4; ++j) bf[j] = Bs[kk][tx * 4 + j];
                    #pragma unroll
                    for (int i = 0; i < 4; ++i)
                        #pragma unroll
                        for (int j = 0; j < 4; ++j)
                            acc[i][j] = fmaf(af[i], bf[j], acc[i][j]);
                }
                __syncthreads();
            }

            #pragma unroll
            for (int i = 0; i < 4; ++i) {
                int row = m0 + ty * 4 + i;
                #pragma unroll
                for (int j = 0; j < 4; ++j)
                    C[(size_t)row * 512 + n0 + tx * 4 + j] = acc[i][j];
            }
            __syncthreads();
        }
    }
}

// ---------------------------------------------------------------------------
// Scalar split-K tiled fp32 GEMM (layers 2-3), 256 threads. (R9-proven)
// ---------------------------------------------------------------------------
template<int BM, int BN, int TM, int TN>
__global__ void __launch_bounds__(256) gemm_split(
        const float* __restrict__ A, const float* __restrict__ Bm,
        int M, int N, int K, int Kc) {
    constexpr int BK = 16;
    constexpr int TX = BN / TN;
    constexpr int TY = BM / TM;
    static_assert(TX * TY == 256, "256 threads");
    static_assert(BN == 64, "B-tile loader assumes BN==64");

    __shared__ float As[BK][BM + 4];
    __shared__ float Bs[BK][BN + 4];

    const int tid = threadIdx.x;
    const int tx = tid % TX, ty = tid / TX;
    const int m0 = blockIdx.y * BM, n0 = blockIdx.x * BN;
    const int k0 = blockIdx.z * Kc;
    float* C = g_part + (size_t)blockIdx.z * M * N;

    const int  a_m   = tid >> 2;
    const int  a_k   = (tid & 3) << 2;
    const bool a_act = (BM * 4 >= 256) ? true : (tid < BM * 4);
    const int  b_k = tid >> 4;
    const int  b_n = (tid & 15) << 2;

    float4 ra = make_float4(0.f, 0.f, 0.f, 0.f);
    float4 rb;

    if (a_act) ra = *(const float4*)(A + (size_t)(m0 + a_m) * K + k0 + a_k);
    rb = *(const float4*)(Bm + (size_t)(k0 + b_k) * N + n0 + b_n);

    float acc[TM][TN];
    #pragma unroll
    for (int i = 0; i < TM; ++i)
        #pragma unroll
        for (int j = 0; j < TN; ++j) acc[i][j] = 0.f;

    const int NT = Kc / BK;
    for (int t = 0; t < NT; ++t) {
        if (a_act) {
            As[a_k + 0][a_m] = ra.x;
            As[a_k + 1][a_m] = ra.y;
            As[a_k + 2][a_m] = ra.z;
            As[a_k + 3][a_m] = ra.w;
        }
        *(float4*)&Bs[b_k][b_n] = rb;
        __syncthreads();

        if (t + 1 < NT) {
            int kk0 = k0 + (t + 1) * BK;
            if (a_act) ra = *(const float4*)(A + (size_t)(m0 + a_m) * K + kk0 + a_k);
            rb = *(const float4*)(Bm + (size_t)(kk0 + b_k) * N + n0 + b_n);
        }

        #pragma unroll
        for (int kk = 0; kk < BK; ++kk) {
            float af[TM], bf[TN];
            #pragma unroll
            for (int i = 0; i < TM; ++i) af[i] = As[kk][ty * TM + i];
            #pragma unroll
            for (int j = 0; j < TN; ++j) bf[j] = Bs[kk][tx * TN + j];
            #pragma unroll
            for (int i = 0; i < TM; ++i)
                #pragma unroll
                for (int j = 0; j < TN; ++j)
                    acc[i][j] = fmaf(af[i], bf[j], acc[i][j]);
        }
        __syncthreads();
    }

    #pragma unroll
    for (int i = 0; i < TM; ++i) {
        int row = m0 + ty * TM + i;
        #pragma unroll
        for (int j = 0; j < TN; ++j)
            C[(size_t)row * N + n0 + tx * TN + j] = acc[i][j];
    }
}

// ---------------------------------------------------------------------------
// out = act(sum_z part[z] + bias [+ C0]); fixed order -> deterministic.
// ---------------------------------------------------------------------------
template<int S, bool RELU, bool ADDC0>
__global__ void combine_k(const float* __restrict__ bias,
                          const float* __restrict__ C0,
                          float* __restrict__ out, int MN4, int N4) {
    int i = blockIdx.x * blockDim.x + threadIdx.x;
    if (i >= MN4) return;
    const float4* p = (const float4*)g_part;
    float4 v = __ldg(&((const float4*)bias)[i % N4]);
    #pragma unroll
    for (int s = 0; s < S; ++s) {
        float4 q = p[(size_t)s * MN4 + i];
        v.x += q.x; v.y += q.y; v.z += q.z; v.w += q.w;
    }
    if (ADDC0) {
        float4 c = ((const float4*)C0)[i];
        v.x += c.x; v.y += c.y; v.z += c.z; v.w += c.w;
    }
    if (RELU) {
        v.x = fmaxf(v.x, 0.f); v.y = fmaxf(v.y, 0.f);
        v.z = fmaxf(v.z, 0.f); v.w = fmaxf(v.w, 0.f);
    }
    ((float4*)out)[i] = v;
}

// ---------------------------------------------------------------------------
extern "C" void kernel_launch(void* const* d_in, const int* in_sizes, int n_in,
                              void* d_out, int out_size) {
    (void)in_sizes; (void)n_in; (void)out_size;

    const float* T_name        = (const float*)d_in[0];
    const float* T_collab      = (const float*)d_in[1];
    const float* T_track_can   = (const float*)d_in[2];
    const float* T_artist_name = (const float*)d_in[3];
    const float* T_track_uri   = (const float*)d_in[4];
    const float* T_track_name  = (const float*)d_in[5];
    const float* T_dur         = (const float*)d_in[6];
    const float* T_album       = (const float*)d_in[7];
    const float* T_apop        = (const float*)d_in[8];
    const float* T_afol        = (const float*)d_in[9];
    const float* T_tpop        = (const float*)d_in[10];
    const float* T_genres      = (const float*)d_in[11];
    const float* W1 = (const float*)d_in[12];
    const float* b1 = (const float*)d_in[13];
    const float* W2 = (const float*)d_in[14];
    const float* b2 = (const float*)d_in[15];
    const float* W3 = (const float*)d_in[16];
    const float* b3 = (const float*)d_in[17];
    const int* id_name         = (const int*)d_in[18];
    const int* id_collab       = (const int*)d_in[19];
    const int* id_track_can    = (const int*)d_in[20];
    const int* seq_artist_name = (const int*)d_in[21];
    const int* seq_track_uri   = (const int*)d_in[22];
    const int* seq_track_name  = (const int*)d_in[23];
    const int* seq_dur         = (const int*)d_in[24];
    const int* seq_album       = (const int*)d_in[25];
    const int* seq_apop        = (const int*)d_in[26];
    const int* seq_afol        = (const int*)d_in[27];
    const int* seq_tpop        = (const int*)d_in[28];
    const int* seq_genres      = (const int*)d_in[29];

    float *Y0, *H1, *H2;
    cudaGetSymbolAddress((void**)&Y0, g_Y0);
    cudaGetSymbolAddress((void**)&H1, g_H1);
    cudaGetSymbolAddress((void**)&H2, g_H2);

    MegaArgs ma;
    ma.tbl[0] = T_name;        ma.idx[0] = id_name;
    ma.tbl[1] = T_track_can;   ma.idx[1] = id_track_can;
    ma.tbl[2] = T_artist_name; ma.idx[2] = seq_artist_name;
    ma.tbl[3] = T_track_uri;   ma.idx[3] = seq_track_uri;
    ma.tbl[4] = T_track_name;  ma.idx[4] = seq_track_name;
    ma.tbl[5] = T_album;       ma.idx[5] = seq_album;
    ma.tbl[6] = T_genres;      ma.idx[6] = seq_genres;
    ma.W1 = W1;

    // independent small-feature fold (cheap, serial at front)
    precompute_P<<<88, 512>>>(T_collab, T_dur, T_apop, T_afol, T_tpop, W1);
    small_pool<<<NB, 128>>>(id_collab, seq_dur, seq_apop, seq_afol, seq_tpop);

    // fused pooling + GEMM1 (persistent, interleaved ticket queue)
    init_mega<<<1, 128>>>();
    mega<<<592, 256>>>(ma);

    // H1 = relu(sum_z part[z] + Y0 + b1)
    combine_k<7, true, true><<<(NB * 512 / 4 + 255) / 256, 256>>>(
        b1, Y0, H1, NB * 512 / 4, 512 / 4);

    // layer 2: [1024,512] @ W2; split-K=2 (Kc=256) -> 256 blocks
    gemm_split<32, 64, 2, 4><<<dim3(256 / 64, NB / 32, 2), 256>>>(
        H1, W2, NB, 256, 512, 256);
    combine_k<2, true, false><<<(NB * 256 / 4 + 255) / 256, 256>>>(
        b2, nullptr, H2, NB * 256 / 4, 256 / 4);

    // layer 3: [1024,256] @ W3; split-K=4 (Kc=64) -> 256 blocks
    gemm_split<32, 64, 2, 4><<<dim3(128 / 64, NB / 32, 4), 256>>>(
        H2, W3, NB, 128, 256, 64);
    combine_k<4, false, false><<<(NB * 128 / 4 + 255) / 256, 256>>>(
        b3, nullptr, (float*)d_out, NB * 128 / 4, 128 / 4);
}